// round 4
// baseline (speedup 1.0000x reference)
#include <cuda_runtime.h>
#include <cstddef>

// Problem constants (fixed by the dataset): B=2, T=1024, C=256, head_dim=2, H=128
#define BB 2
#define TT 1024
#define CC 256
#define HH 128

typedef unsigned long long u64;

// Scratch (no allocations allowed -> __device__ globals)
__device__ float  g_qkv[BB * TT * 3 * CC];        // (2048, 768)
__device__ float2 g_q  [BB * HH * TT];            // normalized q * (log2e/sqrt2) * qn_w
__device__ float  g_kx [BB * HH * TT];            // SoA normalized k / v
__device__ float  g_ky [BB * HH * TT];
__device__ float  g_vx [BB * HH * TT];
__device__ float  g_vy [BB * HH * TT];
__device__ float  g_y  [BB * TT * CC];            // attention output in (b,t,c) layout

// ---------------- f32x2 packed helpers (sm_103a FFMA2 path) ----------------
__device__ __forceinline__ float ex2f(float x) {
    float r; asm("ex2.approx.f32 %0, %1;" : "=f"(r) : "f"(x)); return r;
}
__device__ __forceinline__ u64 pk2(float x, float y) {
    u64 r; asm("mov.b64 %0, {%1, %2};" : "=l"(r) : "r"(__float_as_uint(x)), "r"(__float_as_uint(y)));
    return r;
}
__device__ __forceinline__ void unpk2(u64 v, float& x, float& y) {
    unsigned a, b; asm("mov.b64 {%0, %1}, %2;" : "=r"(a), "=r"(b) : "l"(v));
    x = __uint_as_float(a); y = __uint_as_float(b);
}
__device__ __forceinline__ u64 fma2(u64 a, u64 b, u64 c) {
    u64 d; asm("fma.rn.f32x2 %0, %1, %2, %3;" : "=l"(d) : "l"(a), "l"(b), "l"(c)); return d;
}
__device__ __forceinline__ u64 mul2(u64 a, u64 b) {
    u64 d; asm("mul.rn.f32x2 %0, %1, %2;" : "=l"(d) : "l"(a), "l"(b)); return d;
}
__device__ __forceinline__ u64 add2(u64 a, u64 b) {
    u64 d; asm("add.rn.f32x2 %0, %1, %2;" : "=l"(d) : "l"(a), "l"(b)); return d;
}

// ---------------------------------------------------------------------------
// C[m][n] = sum_k A[m*K+k] * W[n*K+k]   via packed f32x2 FMA.
// 64x64 tile, 256 threads, 4x4 microtile. A rows duplicated in shared so the
// broadcast operand is already packed (no per-k MOVs).
// ---------------------------------------------------------------------------
__global__ void __launch_bounds__(256) sgemm2(const float* __restrict__ A,
                                              const float* __restrict__ W,
                                              float* __restrict__ Cout,
                                              int M, int N, int K)
{
    __shared__ float As[16][128];   // k x (64 rows duplicated: row r at 2r, 2r+1)
    __shared__ float Bs[16][64];    // k x 64 cols
    const int tid = threadIdx.x;
    const int m0 = blockIdx.y * 64, n0 = blockIdx.x * 64;
    const int rg = tid & 15;        // row group: rows 4rg..4rg+3
    const int cg = tid >> 4;        // col group: cols 4cg..4cg+3

    const int lrow = tid >> 2;          // 0..63
    const int lkq  = (tid & 3) * 4;     // 0,4,8,12

    u64 acc[4][2] = {};             // [row i][col-pair j] -> cols 4cg+2j, 4cg+2j+1

    for (int k0 = 0; k0 < K; k0 += 16) {
        float4 av = *(const float4*)(A + (size_t)(m0 + lrow) * K + k0 + lkq);
        float4 wv = *(const float4*)(W + (size_t)(n0 + lrow) * K + k0 + lkq);
        __syncthreads();
        As[lkq + 0][2*lrow] = av.x; As[lkq + 0][2*lrow + 1] = av.x;
        As[lkq + 1][2*lrow] = av.y; As[lkq + 1][2*lrow + 1] = av.y;
        As[lkq + 2][2*lrow] = av.z; As[lkq + 2][2*lrow + 1] = av.z;
        As[lkq + 3][2*lrow] = av.w; As[lkq + 3][2*lrow + 1] = av.w;
        Bs[lkq + 0][lrow] = wv.x; Bs[lkq + 1][lrow] = wv.y;
        Bs[lkq + 2][lrow] = wv.z; Bs[lkq + 3][lrow] = wv.w;
        __syncthreads();
        #pragma unroll
        for (int k = 0; k < 16; k++) {
            const u64* ap = (const u64*)&As[k][8 * rg];   // 4 dup'd row pairs
            const u64* bp = (const u64*)&Bs[k][4 * cg];   // 2 col pairs
            u64 b0 = bp[0], b1 = bp[1];
            u64 a0 = ap[0], a1 = ap[1], a2 = ap[2], a3 = ap[3];
            acc[0][0] = fma2(a0, b0, acc[0][0]); acc[0][1] = fma2(a0, b1, acc[0][1]);
            acc[1][0] = fma2(a1, b0, acc[1][0]); acc[1][1] = fma2(a1, b1, acc[1][1]);
            acc[2][0] = fma2(a2, b0, acc[2][0]); acc[2][1] = fma2(a2, b1, acc[2][1]);
            acc[3][0] = fma2(a3, b0, acc[3][0]); acc[3][1] = fma2(a3, b1, acc[3][1]);
        }
    }
    #pragma unroll
    for (int i = 0; i < 4; i++) {
        float4 v;
        unpk2(acc[i][0], v.x, v.y);
        unpk2(acc[i][1], v.z, v.w);
        *(float4*)(Cout + (size_t)(m0 + 4 * rg + i) * N + n0 + 4 * cg) = v;
    }
}

// ---------------------------------------------------------------------------
// Split qkv + RMSNorm(q,k) over head_dim=2, fold softmax scale*log2e into q,
// repack into SoA per-(b,h) contiguous layouts for the attention kernel.
// ---------------------------------------------------------------------------
__global__ void split_norm(const float* __restrict__ qn_w, const float* __restrict__ kn_w)
{
    int i = blockIdx.x * blockDim.x + threadIdx.x;
    if (i >= BB * HH * TT) return;
    int t = i % TT;
    int h = (i / TT) % HH;
    int b = i / (HH * TT);

    const float* rowp = g_qkv + (size_t)(b * TT + t) * (3 * CC);
    float2 q = *(const float2*)(rowp + 2 * h);
    float2 k = *(const float2*)(rowp + CC + 2 * h);
    float2 v = *(const float2*)(rowp + 2 * CC + 2 * h);

    // log2(e)/sqrt(2): fold softmax scale and base-2 exp conversion into q
    const float L2SCALE = 1.02013946f;
    float rq = rsqrtf(0.5f * (q.x * q.x + q.y * q.y) + 1e-6f);
    float rk = rsqrtf(0.5f * (k.x * k.x + k.y * k.y) + 1e-6f);

    size_t o = (size_t)(b * HH + h) * TT + t;
    g_q[o]  = make_float2(q.x * rq * qn_w[0] * L2SCALE,
                          q.y * rq * qn_w[1] * L2SCALE);
    g_kx[o] = k.x * rk * kn_w[0];
    g_ky[o] = k.y * rk * kn_w[1];
    g_vx[o] = v.x;
    g_vy[o] = v.y;
}

// ---------------------------------------------------------------------------
// Causal attention, head_dim=2. One block per (b*h, 128-row t tile).
// Logits bounded in [-sqrt2, sqrt2] -> no max subtraction; exp via ex2.
// Inner loop: 4 pairs per iteration, packed f32x2 math (MUFU-bound).
// ---------------------------------------------------------------------------
__global__ void __launch_bounds__(128) attn_kernel()
{
    __shared__ float skx[TT], sky[TT], svx[TT], svy[TT];
    const int bh = blockIdx.x;
    const int t0 = blockIdx.y * 128;
    const int s_end = t0 + 128;
    const size_t base = (size_t)bh * TT;

    for (int i = threadIdx.x; i < s_end; i += 128) {
        skx[i] = g_kx[base + i];
        sky[i] = g_ky[base + i];
        svx[i] = g_vx[base + i];
        svy[i] = g_vy[base + i];
    }
    __syncthreads();

    const int t = t0 + threadIdx.x;
    const float2 q = g_q[base + t];
    const u64 qx2 = pk2(q.x, q.x), qy2 = pk2(q.y, q.y);

    u64 n0a = 0, n0b = 0, n1a = 0, n1b = 0, da = 0, db = 0;
    float sn0 = 0.f, sn1 = 0.f, sd = 0.f;

    const int nfull = (t + 1) & ~3;
    int s = 0;
    #pragma unroll 2
    for (; s < nfull; s += 4) {
        const u64* kxp = (const u64*)&skx[s];
        const u64* kyp = (const u64*)&sky[s];
        u64 l01 = fma2(qx2, kxp[0], mul2(qy2, kyp[0]));
        u64 l23 = fma2(qx2, kxp[1], mul2(qy2, kyp[1]));
        float f0, f1, f2, f3;
        unpk2(l01, f0, f1); unpk2(l23, f2, f3);
        u64 p01 = pk2(ex2f(f0), ex2f(f1));
        u64 p23 = pk2(ex2f(f2), ex2f(f3));
        const u64* vxp = (const u64*)&svx[s];
        const u64* vyp = (const u64*)&svy[s];
        n0a = fma2(p01, vxp[0], n0a); n0b = fma2(p23, vxp[1], n0b);
        n1a = fma2(p01, vyp[0], n1a); n1b = fma2(p23, vyp[1], n1b);
        da  = add2(da, p01);          db  = add2(db, p23);
    }
    for (; s <= t; ++s) {
        float p = ex2f(fmaf(q.x, skx[s], q.y * sky[s]));
        sn0 = fmaf(p, svx[s], sn0);
        sn1 = fmaf(p, svy[s], sn1);
        sd += p;
    }

    float a, b2, c, d2, e, f;
    unpk2(add2(n0a, n0b), a, b2);
    unpk2(add2(n1a, n1b), c, d2);
    unpk2(add2(da,  db),  e, f);
    float num0 = a + b2 + sn0;
    float num1 = c + d2 + sn1;
    float den  = e + f + sd;
    float inv  = 1.0f / den;

    const int b = bh >> 7;       // / HH
    const int h = bh & 127;      // % HH
    float* yp = g_y + (size_t)(b * TT + t) * CC + 2 * h;
    yp[0] = num0 * inv;
    yp[1] = num1 * inv;
}

// ---------------------------------------------------------------------------
extern "C" void kernel_launch(void* const* d_in, const int* in_sizes, int n_in,
                              void* d_out, int out_size)
{
    const float* x      = (const float*)d_in[0];   // (2,1024,256)
    const float* w_qkv  = (const float*)d_in[1];   // (768,256)
    const float* w_proj = (const float*)d_in[2];   // (256,256)
    const float* qn_w   = (const float*)d_in[3];   // (2,)
    const float* kn_w   = (const float*)d_in[4];   // (2,)
    float* out = (float*)d_out;                    // (2,1024,256)

    float *qkv_p, *y_p;
    cudaGetSymbolAddress((void**)&qkv_p, g_qkv);
    cudaGetSymbolAddress((void**)&y_p,   g_y);

    // qkv = x @ w_qkv^T : (2048,768)
    sgemm2<<<dim3(768 / 64, 2048 / 64), 256>>>(x, w_qkv, qkv_p, BB * TT, 3 * CC, CC);
    // rmsnorm + repack (SoA)
    split_norm<<<(BB * HH * TT) / 256, 256>>>(qn_w, kn_w);
    // causal attention
    attn_kernel<<<dim3(BB * HH, TT / 128), 128>>>();
    // out = y @ w_proj^T : (2048,256)
    sgemm2<<<dim3(256 / 64, 2048 / 64), 256>>>(y_p, w_proj, out, BB * TT, CC, CC);
}

// round 7
// speedup vs baseline: 1.6284x; 1.6284x over previous
#include <cuda_runtime.h>
#include <cstddef>

// Problem constants (fixed by the dataset): B=2, T=1024, C=256, head_dim=2, H=128
#define BB 2
#define TT 1024
#define CC 256
#define HH 128
#define NBH (BB*HH)      // 256
#define CHUNK 128
#define NCH 8            // TT / CHUNK
#define NF 55            // Taylor-9 features over (qx,qy)
#define NCHAN (NF*3)     // 165: per feature {den, vx, vy}

// Scratch (no allocations allowed -> __device__ globals)
__device__ float  g_qkv[BB * TT * 3 * CC];
__device__ float2 g_q  [NBH * TT];          // normalized q * qn_w * (log2e/sqrt2)
__device__ float  g_kx [NBH * TT];          // SoA normalized k / raw v
__device__ float  g_ky [NBH * TT];
__device__ float  g_vx [NBH * TT];
__device__ float  g_vy [NBH * TT];
__device__ float  g_S  [NBH * NCH * NCHAN]; // exclusive chunk prefix sums (coeff-folded)
__device__ float  g_y  [BB * TT * CC];

// cc[f] = 1/(i! (n-i)!) for feature (n,i), n=0..9, i=0..n  (Taylor exp coeffs x binomials)
__constant__ float c_cc[NF] = {
    1.0f,
    1.0f, 1.0f,
    0.5f, 1.0f, 0.5f,
    0.16666667f, 0.5f, 0.5f, 0.16666667f,
    0.041666668f, 0.16666667f, 0.25f, 0.16666667f, 0.041666668f,
    0.008333334f, 0.041666668f, 0.083333336f, 0.083333336f, 0.041666668f, 0.008333334f,
    0.0013888889f, 0.008333334f, 0.020833334f, 0.027777778f, 0.020833334f, 0.008333334f, 0.0013888889f,
    1.9841270e-4f, 0.0013888889f, 0.0041666667f, 0.0069444445f, 0.0069444445f, 0.0041666667f, 0.0013888889f, 1.9841270e-4f,
    2.4801587e-5f, 1.9841270e-4f, 6.9444446e-4f, 0.0013888889f, 0.0017361111f, 0.0013888889f, 6.9444446e-4f, 1.9841270e-4f, 2.4801587e-5f,
    2.7557319e-6f, 2.4801587e-5f, 9.9206349e-5f, 2.3148148e-4f, 3.4722222e-4f, 3.4722222e-4f, 2.3148148e-4f, 9.9206349e-5f, 2.4801587e-5f, 2.7557319e-6f
};

__device__ __forceinline__ float ex2f(float x) {
    float r; asm("ex2.approx.f32 %0, %1;" : "=f"(r) : "f"(x)); return r;
}

// ---------------------------------------------------------------------------
// C[m][n] = sum_k A[m*K+k] * W[n*K+k].  64x64 tile, 256 threads, 4x4 micro.
// Global loads for the NEXT k-tile are issued before the compute of the
// current tile so LDG latency hides under the 128 FFMAs.
// ---------------------------------------------------------------------------
__global__ void __launch_bounds__(256) sgemm_nt(const float* __restrict__ A,
                                                const float* __restrict__ W,
                                                float* __restrict__ Cout,
                                                int M, int N, int K)
{
    __shared__ float As[16][64];
    __shared__ float Ws[16][64];
    const int tid = threadIdx.x;
    const int tx = tid & 15, ty = tid >> 4;
    const int m0 = blockIdx.y * 64, n0 = blockIdx.x * 64;
    const int row = tid >> 2;          // 0..63
    const int kq  = (tid & 3) * 4;     // 0,4,8,12

    float acc[4][4] = {};
    float4 av = *(const float4*)(A + (size_t)(m0 + row) * K + kq);
    float4 wv = *(const float4*)(W + (size_t)(n0 + row) * K + kq);

    for (int k0 = 0; k0 < K; k0 += 16) {
        __syncthreads();
        As[kq + 0][row] = av.x; As[kq + 1][row] = av.y;
        As[kq + 2][row] = av.z; As[kq + 3][row] = av.w;
        Ws[kq + 0][row] = wv.x; Ws[kq + 1][row] = wv.y;
        Ws[kq + 2][row] = wv.z; Ws[kq + 3][row] = wv.w;
        __syncthreads();
        if (k0 + 16 < K) {
            av = *(const float4*)(A + (size_t)(m0 + row) * K + k0 + 16 + kq);
            wv = *(const float4*)(W + (size_t)(n0 + row) * K + k0 + 16 + kq);
        }
        #pragma unroll
        for (int k = 0; k < 16; k++) {
            float4 a = *(const float4*)&As[k][ty * 4];
            float4 b = *(const float4*)&Ws[k][tx * 4];
            float ar[4] = {a.x, a.y, a.z, a.w};
            float br[4] = {b.x, b.y, b.z, b.w};
            #pragma unroll
            for (int i = 0; i < 4; i++)
                #pragma unroll
                for (int j = 0; j < 4; j++)
                    acc[i][j] = fmaf(ar[i], br[j], acc[i][j]);
        }
    }
    #pragma unroll
    for (int i = 0; i < 4; i++) {
        float4 v = make_float4(acc[i][0], acc[i][1], acc[i][2], acc[i][3]);
        *(float4*)(Cout + (size_t)(m0 + ty * 4 + i) * N + n0 + tx * 4) = v;
    }
}

// 32x64 tile, 128 threads variant (doubles block count for small-N GEMMs)
__global__ void __launch_bounds__(128) sgemm_nt32(const float* __restrict__ A,
                                                  const float* __restrict__ W,
                                                  float* __restrict__ Cout,
                                                  int M, int N, int K)
{
    __shared__ float As[16][32];
    __shared__ float Ws[16][64];
    const int tid = threadIdx.x;
    const int tx = tid & 15, ty = tid >> 4;     // 16 x 8
    const int m0 = blockIdx.y * 32, n0 = blockIdx.x * 64;
    const int arow = tid >> 2;                  // 0..31
    const int kq   = (tid & 3) * 4;

    float acc[4][4] = {};
    float4 av  = *(const float4*)(A + (size_t)(m0 + arow) * K + kq);
    float4 wv0 = *(const float4*)(W + (size_t)(n0 + arow) * K + kq);
    float4 wv1 = *(const float4*)(W + (size_t)(n0 + arow + 32) * K + kq);

    for (int k0 = 0; k0 < K; k0 += 16) {
        __syncthreads();
        As[kq + 0][arow] = av.x; As[kq + 1][arow] = av.y;
        As[kq + 2][arow] = av.z; As[kq + 3][arow] = av.w;
        Ws[kq + 0][arow] = wv0.x; Ws[kq + 1][arow] = wv0.y;
        Ws[kq + 2][arow] = wv0.z; Ws[kq + 3][arow] = wv0.w;
        Ws[kq + 0][arow + 32] = wv1.x; Ws[kq + 1][arow + 32] = wv1.y;
        Ws[kq + 2][arow + 32] = wv1.z; Ws[kq + 3][arow + 32] = wv1.w;
        __syncthreads();
        if (k0 + 16 < K) {
            av  = *(const float4*)(A + (size_t)(m0 + arow) * K + k0 + 16 + kq);
            wv0 = *(const float4*)(W + (size_t)(n0 + arow) * K + k0 + 16 + kq);
            wv1 = *(const float4*)(W + (size_t)(n0 + arow + 32) * K + k0 + 16 + kq);
        }
        #pragma unroll
        for (int k = 0; k < 16; k++) {
            float4 a = *(const float4*)&As[k][ty * 4];
            float4 b = *(const float4*)&Ws[k][tx * 4];
            float ar[4] = {a.x, a.y, a.z, a.w};
            float br[4] = {b.x, b.y, b.z, b.w};
            #pragma unroll
            for (int i = 0; i < 4; i++)
                #pragma unroll
                for (int j = 0; j < 4; j++)
                    acc[i][j] = fmaf(ar[i], br[j], acc[i][j]);
        }
    }
    #pragma unroll
    for (int i = 0; i < 4; i++) {
        float4 v = make_float4(acc[i][0], acc[i][1], acc[i][2], acc[i][3]);
        *(float4*)(Cout + (size_t)(m0 + ty * 4 + i) * N + n0 + tx * 4) = v;
    }
}

// ---------------------------------------------------------------------------
// Split qkv + RMSNorm(q,k) over head_dim=2, fold softmax scale*log2e into q.
// ---------------------------------------------------------------------------
__global__ void split_norm(const float* __restrict__ qn_w, const float* __restrict__ kn_w)
{
    int i = blockIdx.x * blockDim.x + threadIdx.x;
    if (i >= NBH * TT) return;
    int t = i % TT;
    int h = (i / TT) % HH;
    int b = i / (HH * TT);

    const float* rowp = g_qkv + (size_t)(b * TT + t) * (3 * CC);
    float2 q = *(const float2*)(rowp + 2 * h);
    float2 k = *(const float2*)(rowp + CC + 2 * h);
    float2 v = *(const float2*)(rowp + 2 * CC + 2 * h);

    const float L2SCALE = 1.02013946f;   // log2(e)/sqrt(2)
    float rq = rsqrtf(0.5f * (q.x * q.x + q.y * q.y) + 1e-6f);
    float rk = rsqrtf(0.5f * (k.x * k.x + k.y * k.y) + 1e-6f);

    size_t o = (size_t)(b * HH + h) * TT + t;
    g_q[o]  = make_float2(q.x * rq * qn_w[0] * L2SCALE,
                          q.y * rq * qn_w[1] * L2SCALE);
    g_kx[o] = k.x * rk * kn_w[0];
    g_ky[o] = k.y * rk * kn_w[1];
    g_vx[o] = v.x;
    g_vy[o] = v.y;
}

// ---------------------------------------------------------------------------
// Per-(bh): for each 128-chunk compute 165 feature-channel sums
// (psi_f(k_s) x {1, vx, vy}), then exclusive-scan over chunks, folding the
// Taylor coefficients into the stored prefix.
// ---------------------------------------------------------------------------
__global__ void __launch_bounds__(128) featscan()
{
    __shared__ float sPsi[NF * 132];           // [f][s], padded stride
    __shared__ float svx[CHUNK], svy[CHUNK];
    __shared__ float sG[NCH][NCHAN];
    const int bh = blockIdx.x, tid = threadIdx.x;
    const size_t base = (size_t)bh * TT;

    for (int c = 0; c < NCH; c++) {
        int s = c * CHUNK + tid;
        float kx = g_kx[base + s], ky = g_ky[base + s];
        float vx = g_vx[base + s], vy = g_vy[base + s];
        __syncthreads();                        // protect prev chunk's readers
        svx[tid] = vx; svy[tid] = vy;
        float row[10];
        row[0] = 1.0f;
        sPsi[0 * 132 + tid] = 1.0f;
        int fb = 1;
        #pragma unroll
        for (int n = 1; n <= 9; n++) {
            row[n] = row[n - 1] * kx;
            #pragma unroll
            for (int i = n - 1; i >= 0; i--) row[i] *= ky;
            #pragma unroll
            for (int i = 0; i <= n; i++) sPsi[(fb + i) * 132 + tid] = row[i];
            fb += n + 1;
        }
        __syncthreads();
        for (int ch = tid; ch < NCHAN; ch += 128) {
            int f = ch / 3, w = ch - 3 * f;
            const float* pp = &sPsi[f * 132];
            float acc = 0.0f;
            if (w == 0) {
                #pragma unroll 8
                for (int ss = 0; ss < CHUNK; ss++) acc += pp[ss];
            } else {
                const float* wp = (w == 1) ? svx : svy;
                #pragma unroll 8
                for (int ss = 0; ss < CHUNK; ss++) acc = fmaf(pp[ss], wp[ss], acc);
            }
            sG[c][ch] = acc;
        }
    }
    __syncthreads();
    for (int ch = tid; ch < NCHAN; ch += 128) {
        int f = ch / 3;
        float coef = c_cc[f];
        float excl = 0.0f;
        #pragma unroll
        for (int c = 0; c < NCH; c++) {
            g_S[((size_t)bh * NCH + c) * NCHAN + ch] = excl * coef;
            excl += sG[c][ch];
        }
    }
}

// ---------------------------------------------------------------------------
// Chunked causal attention: exact ex2 within own chunk + rank-55 feature dot
// against the exclusive chunk prefix for everything before the chunk.
// ---------------------------------------------------------------------------
__global__ void __launch_bounds__(128) attn2()
{
    __shared__ float skx[CHUNK], sky[CHUNK], svx[CHUNK], svy[CHUNK];
    __shared__ float sS[NCHAN];
    const int bh = blockIdx.x, c = blockIdx.y, tid = threadIdx.x;
    const size_t base = (size_t)bh * TT;
    const int t = c * CHUNK + tid;

    skx[tid] = g_kx[base + t];
    sky[tid] = g_ky[base + t];
    svx[tid] = g_vx[base + t];
    svy[tid] = g_vy[base + t];
    const float* Sp = &g_S[((size_t)bh * NCH + c) * NCHAN];
    sS[tid] = Sp[tid];
    if (tid < NCHAN - 128) sS[tid + 128] = Sp[tid + 128];
    __syncthreads();

    const float2 q = g_q[base + t];

    // exact intra-chunk (logits pre-scaled by log2e/sqrt2 -> bare ex2)
    float a0[4] = {0.f, 0.f, 0.f, 0.f};
    float a1[4] = {0.f, 0.f, 0.f, 0.f};
    float ad[4] = {0.f, 0.f, 0.f, 0.f};
    const int n = tid + 1, n4 = n & ~3;
    int s = 0;
    for (; s < n4; s += 4) {
        #pragma unroll
        for (int j = 0; j < 4; j++) {
            float p = ex2f(fmaf(q.x, skx[s + j], q.y * sky[s + j]));
            a0[j] = fmaf(p, svx[s + j], a0[j]);
            a1[j] = fmaf(p, svy[s + j], a1[j]);
            ad[j] += p;
        }
    }
    for (; s < n; ++s) {
        float p = ex2f(fmaf(q.x, skx[s], q.y * sky[s]));
        a0[0] = fmaf(p, svx[s], a0[0]);
        a1[0] = fmaf(p, svy[s], a1[0]);
        ad[0] += p;
    }
    float num0 = (a0[0] + a0[1]) + (a0[2] + a0[3]);
    float num1 = (a1[0] + a1[1]) + (a1[2] + a1[3]);
    float den  = (ad[0] + ad[1]) + (ad[2] + ad[3]);

    // inter-chunk via Taylor features of exp(u), u = (q/sqrt2)·k, |u|<=sqrt2
    const float LN2 = 0.69314718f;               // undo the log2e in stored q
    const float qx = q.x * LN2, qy = q.y * LN2;
    float row[10];
    row[0] = 1.0f;
    den  += sS[0];
    num0 += sS[1];
    num1 += sS[2];
    int fb = 1;
    #pragma unroll
    for (int nn = 1; nn <= 9; nn++) {
        row[nn] = row[nn - 1] * qx;
        #pragma unroll
        for (int i = nn - 1; i >= 0; i--) row[i] *= qy;
        #pragma unroll
        for (int i = 0; i <= nn; i++) {
            int f3 = 3 * (fb + i);
            den  = fmaf(row[i], sS[f3],     den);
            num0 = fmaf(row[i], sS[f3 + 1], num0);
            num1 = fmaf(row[i], sS[f3 + 2], num1);
        }
        fb += nn + 1;
    }

    float inv = 1.0f / den;
    const int b = bh >> 7, h = bh & 127;
    float* yp = g_y + (size_t)(b * TT + t) * CC + 2 * h;
    yp[0] = num0 * inv;
    yp[1] = num1 * inv;
}

// ---------------------------------------------------------------------------
extern "C" void kernel_launch(void* const* d_in, const int* in_sizes, int n_in,
                              void* d_out, int out_size)
{
    const float* x      = (const float*)d_in[0];   // (2,1024,256)
    const float* w_qkv  = (const float*)d_in[1];   // (768,256)
    const float* w_proj = (const float*)d_in[2];   // (256,256)
    const float* qn_w   = (const float*)d_in[3];   // (2,)
    const float* kn_w   = (const float*)d_in[4];   // (2,)
    float* out = (float*)d_out;                    // (2,1024,256)

    float *qkv_p, *y_p;
    cudaGetSymbolAddress((void**)&qkv_p, g_qkv);
    cudaGetSymbolAddress((void**)&y_p,   g_y);

    // qkv = x @ w_qkv^T : (2048,768)
    sgemm_nt<<<dim3(768 / 64, 2048 / 64), 256>>>(x, w_qkv, qkv_p, BB * TT, 3 * CC, CC);
    // rmsnorm + repack (SoA)
    split_norm<<<(NBH * TT) / 256, 256>>>(qn_w, kn_w);
    // chunk feature sums + exclusive scan
    featscan<<<NBH, 128>>>();
    // chunked causal attention
    attn2<<<dim3(NBH, NCH), 128>>>();
    // out = y @ w_proj^T : (2048,256)
    sgemm_nt32<<<dim3(256 / 64, 2048 / 32), 128>>>(y_p, w_proj, out, BB * TT, CC, CC);
}

// round 8
// speedup vs baseline: 1.9674x; 1.2082x over previous
#include <cuda_runtime.h>
#include <cstddef>

// Problem constants (fixed by the dataset): B=2, T=1024, C=256, head_dim=2, H=128
#define BB 2
#define TT 1024
#define CC 256
#define HH 128
#define NBH (BB*HH)      // 256
#define CH2 32           // fine chunk for intra-exact attention
#define NCH2 (TT/CH2)    // 32 chunks
#define NFF 17           // Fourier features: 1, {cos,sin}(m*beta) m=1..8
#define NCHF (NFF*3)     // 51 channels: per feature {den, vx, vy}

// Scratch (no allocations allowed -> __device__ globals)
__device__ float  g_qkv[BB * TT * 3 * CC];
__device__ float2 g_q  [NBH * TT];          // normalized q * qn_w * (log2e/sqrt2)
__device__ float  g_kx [NBH * TT];          // SoA normalized k / raw v
__device__ float  g_ky [NBH * TT];
__device__ float  g_vx [NBH * TT];
__device__ float  g_vy [NBH * TT];
__device__ float  g_y  [BB * TT * CC];

// Fourier coefficients: C0=I0(sqrt2), Cm=2*Im(sqrt2); f=0 -> C0, f=2m-1,2m -> Cm
__constant__ float c_CM[NFF] = {
    1.56608293f,
    1.79848892f, 1.79848892f,
    0.58871897f, 0.58871897f,
    0.13333993f, 0.13333993f,
    0.02300557f, 0.02300557f,
    3.2007638e-3f, 3.2007638e-3f,
    3.7280500e-4f, 3.7280500e-4f,
    3.7328000e-5f, 3.7328000e-5f,
    3.2767400e-6f, 3.2767400e-6f
};

__device__ __forceinline__ float ex2f(float x) {
    float r; asm("ex2.approx.f32 %0, %1;" : "=f"(r) : "f"(x)); return r;
}

// ---------------------------------------------------------------------------
// C[m][n] = sum_k A[m*K+k] * W[n*K+k].  64x64 tile, 256 threads, 4x4 micro,
// next-k-tile global prefetch.
// ---------------------------------------------------------------------------
__global__ void __launch_bounds__(256) sgemm_nt(const float* __restrict__ A,
                                                const float* __restrict__ W,
                                                float* __restrict__ Cout,
                                                int M, int N, int K)
{
    __shared__ float As[16][64];
    __shared__ float Ws[16][64];
    const int tid = threadIdx.x;
    const int tx = tid & 15, ty = tid >> 4;
    const int m0 = blockIdx.y * 64, n0 = blockIdx.x * 64;
    const int row = tid >> 2;
    const int kq  = (tid & 3) * 4;

    float acc[4][4] = {};
    float4 av = *(const float4*)(A + (size_t)(m0 + row) * K + kq);
    float4 wv = *(const float4*)(W + (size_t)(n0 + row) * K + kq);

    for (int k0 = 0; k0 < K; k0 += 16) {
        __syncthreads();
        As[kq + 0][row] = av.x; As[kq + 1][row] = av.y;
        As[kq + 2][row] = av.z; As[kq + 3][row] = av.w;
        Ws[kq + 0][row] = wv.x; Ws[kq + 1][row] = wv.y;
        Ws[kq + 2][row] = wv.z; Ws[kq + 3][row] = wv.w;
        __syncthreads();
        if (k0 + 16 < K) {
            av = *(const float4*)(A + (size_t)(m0 + row) * K + k0 + 16 + kq);
            wv = *(const float4*)(W + (size_t)(n0 + row) * K + k0 + 16 + kq);
        }
        #pragma unroll
        for (int k = 0; k < 16; k++) {
            float4 a = *(const float4*)&As[k][ty * 4];
            float4 b = *(const float4*)&Ws[k][tx * 4];
            float ar[4] = {a.x, a.y, a.z, a.w};
            float br[4] = {b.x, b.y, b.z, b.w};
            #pragma unroll
            for (int i = 0; i < 4; i++)
                #pragma unroll
                for (int j = 0; j < 4; j++)
                    acc[i][j] = fmaf(ar[i], br[j], acc[i][j]);
        }
    }
    #pragma unroll
    for (int i = 0; i < 4; i++) {
        float4 v = make_float4(acc[i][0], acc[i][1], acc[i][2], acc[i][3]);
        *(float4*)(Cout + (size_t)(m0 + ty * 4 + i) * N + n0 + tx * 4) = v;
    }
}

// 32x64 tile, 128 threads variant (more blocks for small-N GEMMs)
__global__ void __launch_bounds__(128) sgemm_nt32(const float* __restrict__ A,
                                                  const float* __restrict__ W,
                                                  float* __restrict__ Cout,
                                                  int M, int N, int K)
{
    __shared__ float As[16][32];
    __shared__ float Ws[16][64];
    const int tid = threadIdx.x;
    const int tx = tid & 15, ty = tid >> 4;
    const int m0 = blockIdx.y * 32, n0 = blockIdx.x * 64;
    const int arow = tid >> 2;
    const int kq   = (tid & 3) * 4;

    float acc[4][4] = {};
    float4 av  = *(const float4*)(A + (size_t)(m0 + arow) * K + kq);
    float4 wv0 = *(const float4*)(W + (size_t)(n0 + arow) * K + kq);
    float4 wv1 = *(const float4*)(W + (size_t)(n0 + arow + 32) * K + kq);

    for (int k0 = 0; k0 < K; k0 += 16) {
        __syncthreads();
        As[kq + 0][arow] = av.x; As[kq + 1][arow] = av.y;
        As[kq + 2][arow] = av.z; As[kq + 3][arow] = av.w;
        Ws[kq + 0][arow] = wv0.x; Ws[kq + 1][arow] = wv0.y;
        Ws[kq + 2][arow] = wv0.z; Ws[kq + 3][arow] = wv0.w;
        Ws[kq + 0][arow + 32] = wv1.x; Ws[kq + 1][arow + 32] = wv1.y;
        Ws[kq + 2][arow + 32] = wv1.z; Ws[kq + 3][arow + 32] = wv1.w;
        __syncthreads();
        if (k0 + 16 < K) {
            av  = *(const float4*)(A + (size_t)(m0 + arow) * K + k0 + 16 + kq);
            wv0 = *(const float4*)(W + (size_t)(n0 + arow) * K + k0 + 16 + kq);
            wv1 = *(const float4*)(W + (size_t)(n0 + arow + 32) * K + k0 + 16 + kq);
        }
        #pragma unroll
        for (int k = 0; k < 16; k++) {
            float4 a = *(const float4*)&As[k][ty * 4];
            float4 b = *(const float4*)&Ws[k][tx * 4];
            float ar[4] = {a.x, a.y, a.z, a.w};
            float br[4] = {b.x, b.y, b.z, b.w};
            #pragma unroll
            for (int i = 0; i < 4; i++)
                #pragma unroll
                for (int j = 0; j < 4; j++)
                    acc[i][j] = fmaf(ar[i], br[j], acc[i][j]);
        }
    }
    #pragma unroll
    for (int i = 0; i < 4; i++) {
        float4 v = make_float4(acc[i][0], acc[i][1], acc[i][2], acc[i][3]);
        *(float4*)(Cout + (size_t)(m0 + ty * 4 + i) * N + n0 + tx * 4) = v;
    }
}

// ---------------------------------------------------------------------------
// Split qkv + RMSNorm(q,k) over head_dim=2, fold softmax scale*log2e into q.
// ---------------------------------------------------------------------------
__global__ void split_norm(const float* __restrict__ qn_w, const float* __restrict__ kn_w)
{
    int i = blockIdx.x * blockDim.x + threadIdx.x;
    if (i >= NBH * TT) return;
    int t = i % TT;
    int h = (i / TT) % HH;
    int b = i / (HH * TT);

    const float* rowp = g_qkv + (size_t)(b * TT + t) * (3 * CC);
    float2 q = *(const float2*)(rowp + 2 * h);
    float2 k = *(const float2*)(rowp + CC + 2 * h);
    float2 v = *(const float2*)(rowp + 2 * CC + 2 * h);

    const float L2SCALE = 1.02013946f;   // log2(e)/sqrt(2)
    float rq = rsqrtf(0.5f * (q.x * q.x + q.y * q.y) + 1e-6f);
    float rk = rsqrtf(0.5f * (k.x * k.x + k.y * k.y) + 1e-6f);

    size_t o = (size_t)(b * HH + h) * TT + t;
    g_q[o]  = make_float2(q.x * rq * qn_w[0] * L2SCALE,
                          q.y * rq * qn_w[1] * L2SCALE);
    g_kx[o] = k.x * rk * kn_w[0];
    g_ky[o] = k.y * rk * kn_w[1];
    g_vx[o] = v.x;
    g_vy[o] = v.y;
}

// ---------------------------------------------------------------------------
// Fused Fourier attention. One 128-thread block per (b,h).
// Phase 1: per-32-chunk channel sums of psi_m(k)x{1,vx,vy} (51 channels).
// Phase 2: in-shared exclusive chunk scan, Bessel coefficients folded in.
// Phase 3: per query: exact ex2 over own chunk (warp=chunk) + 51-channel
//          Fourier dot against the exclusive prefix.
// ---------------------------------------------------------------------------
__global__ void __launch_bounds__(128) fourier_attn()
{
    __shared__ float  sPsi[NFF][132];       // feature x position (one 128-tile)
    __shared__ float  svx[128], svy[128];
    __shared__ float  sG[NCH2][NCHF];       // chunk channel sums -> excl prefix
    __shared__ float4 skv[TT];              // all (kx,ky,vx,vy) for this bh
    const int bh = blockIdx.x, tid = threadIdx.x;
    const int warp = tid >> 5, lane = tid & 31;
    const size_t base = (size_t)bh * TT;

    // ---- Phase 1: chunk feature-channel sums ----
    for (int it = 0; it < 8; it++) {
        int s = it * 128 + tid;
        float kx = g_kx[base + s], ky = g_ky[base + s];
        float vx = g_vx[base + s], vy = g_vy[base + s];
        __syncthreads();                    // previous iter's readers done
        skv[s] = make_float4(kx, ky, vx, vy);
        svx[tid] = vx; svy[tid] = vy;
        // k on radius-sqrt2 circle: cos(beta)=kx/sqrt2, sin(beta)=ky/sqrt2
        float cb = kx * 0.70710678f, sb = ky * 0.70710678f;
        float c2b = cb + cb;
        sPsi[0][tid] = 1.0f;
        sPsi[1][tid] = cb;
        sPsi[2][tid] = sb;
        float cp = 1.0f, sp = 0.0f, cc = cb, cs = sb;
        #pragma unroll
        for (int m = 2; m <= 8; m++) {      // Chebyshev recurrence
            float cn = fmaf(c2b, cc, -cp);
            float sn = fmaf(c2b, cs, -sp);
            sPsi[2 * m - 1][tid] = cn;
            sPsi[2 * m][tid]     = sn;
            cp = cc; sp = cs; cc = cn; cs = sn;
        }
        __syncthreads();
        // 4 chunks x 51 channels = 204 reduction tasks
        for (int task = tid; task < 4 * NCHF; task += 128) {
            int lc = task / NCHF;
            int ch = task - lc * NCHF;
            int f  = ch / 3, w = ch - 3 * f;
            const float4* pp4 = (const float4*)&sPsi[f][lc * 32];
            float acc = 0.0f;
            if (w == 0) {
                #pragma unroll
                for (int j = 0; j < 8; j++) {
                    float4 v = pp4[j];
                    acc += (v.x + v.y) + (v.z + v.w);
                }
            } else {
                const float4* wp4 = (const float4*)((w == 1 ? svx : svy) + lc * 32);
                #pragma unroll
                for (int j = 0; j < 8; j++) {
                    float4 v = pp4[j], u = wp4[j];
                    acc = fmaf(v.x, u.x, acc); acc = fmaf(v.y, u.y, acc);
                    acc = fmaf(v.z, u.z, acc); acc = fmaf(v.w, u.w, acc);
                }
            }
            sG[it * 4 + lc][ch] = acc;
        }
    }
    __syncthreads();

    // ---- Phase 2: exclusive scan over chunks, fold Bessel coefficient ----
    if (tid < NCHF) {
        float coef = c_CM[tid / 3];
        float excl = 0.0f;
        #pragma unroll
        for (int c = 0; c < NCH2; c++) {
            float v = sG[c][tid];
            sG[c][tid] = excl * coef;
            excl += v;
        }
    }
    __syncthreads();

    // ---- Phase 3: attention (warp = chunk within each 128-query tile) ----
    const int b = bh >> 7, h = bh & 127;
    for (int it = 0; it < 8; it++) {
        int t = it * 128 + tid;
        float2 q = g_q[base + t];

        const float4* kp = &skv[(it * 4 + warp) << 5];
        float num0 = 0.f, num1 = 0.f, den = 0.f;

        // exact intra-chunk (q pre-scaled by log2e/sqrt2 -> bare ex2)
        int n = lane + 1, n4 = n & ~3;
        int s = 0;
        for (; s < n4; s += 4) {
            #pragma unroll
            for (int j = 0; j < 4; j++) {
                float4 kv = kp[s + j];
                float p = ex2f(fmaf(q.x, kv.x, q.y * kv.y));
                num0 = fmaf(p, kv.z, num0);
                num1 = fmaf(p, kv.w, num1);
                den += p;
            }
        }
        for (; s < n; s++) {
            float4 kv = kp[s];
            float p = ex2f(fmaf(q.x, kv.x, q.y * kv.y));
            num0 = fmaf(p, kv.z, num0);
            num1 = fmaf(p, kv.w, num1);
            den += p;
        }

        // inter-chunk Fourier dot: cos(alpha)=q.x*ln2 (undo log2e/sqrt2 * sqrt2)
        const float* S = sG[it * 4 + warp];
        float ca = q.x * 0.69314718f, sa = q.y * 0.69314718f;
        den  += S[0];
        num0 += S[1];
        num1 += S[2];
        float c2a = ca + ca;
        float cp = 1.f, sp = 0.f, cc = ca, cs = sa;
        #pragma unroll
        for (int m = 1; m <= 8; m++) {
            int b3 = 3 * (2 * m - 1);
            den  = fmaf(cc, S[b3 + 0], den);
            num0 = fmaf(cc, S[b3 + 1], num0);
            num1 = fmaf(cc, S[b3 + 2], num1);
            den  = fmaf(cs, S[b3 + 3], den);
            num0 = fmaf(cs, S[b3 + 4], num0);
            num1 = fmaf(cs, S[b3 + 5], num1);
            float cn = fmaf(c2a, cc, -cp);
            float sn = fmaf(c2a, cs, -sp);
            cp = cc; sp = cs; cc = cn; cs = sn;
        }

        float inv = 1.0f / den;
        float* yp = g_y + (size_t)(b * TT + t) * CC + 2 * h;
        yp[0] = num0 * inv;
        yp[1] = num1 * inv;
    }
}

// ---------------------------------------------------------------------------
extern "C" void kernel_launch(void* const* d_in, const int* in_sizes, int n_in,
                              void* d_out, int out_size)
{
    const float* x      = (const float*)d_in[0];   // (2,1024,256)
    const float* w_qkv  = (const float*)d_in[1];   // (768,256)
    const float* w_proj = (const float*)d_in[2];   // (256,256)
    const float* qn_w   = (const float*)d_in[3];   // (2,)
    const float* kn_w   = (const float*)d_in[4];   // (2,)
    float* out = (float*)d_out;                    // (2,1024,256)

    float *qkv_p, *y_p;
    cudaGetSymbolAddress((void**)&qkv_p, g_qkv);
    cudaGetSymbolAddress((void**)&y_p,   g_y);

    // qkv = x @ w_qkv^T : (2048,768)
    sgemm_nt<<<dim3(768 / 64, 2048 / 64), 256>>>(x, w_qkv, qkv_p, BB * TT, 3 * CC, CC);
    // rmsnorm + repack (SoA)
    split_norm<<<(NBH * TT) / 256, 256>>>(qn_w, kn_w);
    // fused Fourier attention
    fourier_attn<<<NBH, 128>>>();
    // out = y @ w_proj^T : (2048,256)
    sgemm_nt32<<<dim3(256 / 64, 2048 / 32), 128>>>(y_p, w_proj, out, BB * TT, CC, CC);
}

// round 12
// speedup vs baseline: 2.5179x; 1.2798x over previous
#include <cuda_runtime.h>
#include <cuda_bf16.h>
#include <cstdint>
#include <cstddef>

// Problem constants: B=2, T=1024, C=256, head_dim=2, H=128
#define BB 2
#define TT 1024
#define CC 256
#define HH 128
#define NBH (BB*HH)      // 256
#define NCH2 32          // 32-chunks for intra-exact attention
#define NFF 17           // Fourier features: 1, {cos,sin}(m*beta) m=1..8
#define NCHF (NFF*3)     // 51 channels

// Scratch (no allocations allowed -> __device__ globals)
__device__ float2 g_q  [NBH * TT];
__device__ float  g_kx [NBH * TT];
__device__ float  g_ky [NBH * TT];
__device__ float  g_vx [NBH * TT];
__device__ float  g_vy [NBH * TT];
__device__ float  g_y  [BB * TT * CC];

// Fourier coefficients: C0=I0(sqrt2), Cm=2*Im(sqrt2)
__constant__ float c_CM[NFF] = {
    1.56608293f,
    1.79848892f, 1.79848892f,
    0.58871897f, 0.58871897f,
    0.13333993f, 0.13333993f,
    0.02300557f, 0.02300557f,
    3.2007638e-3f, 3.2007638e-3f,
    3.7280500e-4f, 3.7280500e-4f,
    3.7328000e-5f, 3.7328000e-5f,
    3.2767400e-6f, 3.2767400e-6f
};

__device__ __forceinline__ float ex2f(float x) {
    float r; asm("ex2.approx.f32 %0, %1;" : "=f"(r) : "f"(x)); return r;
}

// Portable Ampere-style bf16 MMA (valid PTX for plain sm_103 target)
#define MMA16816(c, a, b) \
    asm volatile("mma.sync.aligned.m16n8k16.row.col.f32.bf16.bf16.f32 " \
        "{%0,%1,%2,%3}, {%4,%5,%6,%7}, {%8,%9}, {%0,%1,%2,%3};" \
        : "+f"((c)[0]), "+f"((c)[1]), "+f"((c)[2]), "+f"((c)[3]) \
        : "r"((a)[0]), "r"((a)[1]), "r"((a)[2]), "r"((a)[3]), \
          "r"((b)[0]), "r"((b)[1]))

// Shared tile geometry: bf16 [rows][64] with XOR swizzle on bits 4-6.
// byte address = row*128 + (colbyte ^ ((row&7)<<4))
__device__ __forceinline__ int swzb(int row, int colbyte) {
    return row * 128 + (colbyte ^ ((row & 7) << 4));
}

// smem layout (48KB exactly, static)
#define OFF_AH 0
#define OFF_AL 16384
#define OFF_BH 32768
#define OFF_BL 40960

// ---------------------------------------------------------------------------
// Shared mainloop body: acc[4][2][4] += A[m0..m0+127][0..255] * W[n0..][...]^T
// (bf16 hi/lo 3-product split).  256 threads, 8 warps as 2(m) x 4(n).
// ---------------------------------------------------------------------------
__device__ __forceinline__ void mma_nt_256(unsigned char* sm,
                                           const float* __restrict__ A,
                                           const float* __restrict__ W,
                                           int m0, int n0,
                                           float acc[4][2][4])
{
    const int tid = threadIdx.x;
    const int wid = tid >> 5, lane = tid & 31;
    const int wm = wid & 1, wn = wid >> 1;
    const int g = lane >> 2, tg = lane & 3;

    for (int ci = 0; ci < 4; ci++) {
        const int k0 = ci * 64;
        __syncthreads();                 // previous chunk fully consumed
        // load fp32 pairs, split to bf16 hi/lo, store swizzled
        for (int p = tid; p < 6144; p += 256) {
            const bool isA = p < 4096;
            const int q = isA ? p : p - 4096;
            const int row = q >> 5, pr = q & 31;
            const float* src = isA ? (A + (size_t)(m0 + row) * 256 + k0 + 2 * pr)
                                   : (W + (size_t)(n0 + row) * 256 + k0 + 2 * pr);
            float2 a = *(const float2*)src;
            __nv_bfloat162 h2 = __floats2bfloat162_rn(a.x, a.y);
            float hx = __bfloat162float(h2.x), hy = __bfloat162float(h2.y);
            __nv_bfloat162 l2 = __floats2bfloat162_rn(a.x - hx, a.y - hy);
            uint32_t hw = *reinterpret_cast<uint32_t*>(&h2);
            uint32_t lw = *reinterpret_cast<uint32_t*>(&l2);
            int off = swzb(row, pr * 4);
            if (isA) {
                *(uint32_t*)(sm + OFF_AH + off) = hw;
                *(uint32_t*)(sm + OFF_AL + off) = lw;
            } else {
                *(uint32_t*)(sm + OFF_BH + off) = hw;
                *(uint32_t*)(sm + OFF_BL + off) = lw;
            }
        }
        __syncthreads();

        #pragma unroll
        for (int ks = 0; ks < 4; ks++) {
            const int cb = ks * 32 + tg * 4;
            uint32_t ah[4][4], al[4][4], bh[2][2], bl[2][2];
            #pragma unroll
            for (int i = 0; i < 4; i++) {
                int r = wm * 64 + i * 16 + g;
                int o00 = swzb(r, cb), o10 = swzb(r + 8, cb);
                int o01 = swzb(r, cb + 16), o11 = swzb(r + 8, cb + 16);
                ah[i][0] = *(const uint32_t*)(sm + OFF_AH + o00);
                ah[i][1] = *(const uint32_t*)(sm + OFF_AH + o10);
                ah[i][2] = *(const uint32_t*)(sm + OFF_AH + o01);
                ah[i][3] = *(const uint32_t*)(sm + OFF_AH + o11);
                al[i][0] = *(const uint32_t*)(sm + OFF_AL + o00);
                al[i][1] = *(const uint32_t*)(sm + OFF_AL + o10);
                al[i][2] = *(const uint32_t*)(sm + OFF_AL + o01);
                al[i][3] = *(const uint32_t*)(sm + OFF_AL + o11);
            }
            #pragma unroll
            for (int j = 0; j < 2; j++) {
                int rn = wn * 16 + j * 8 + g;
                int o0 = swzb(rn, cb), o1 = swzb(rn, cb + 16);
                bh[j][0] = *(const uint32_t*)(sm + OFF_BH + o0);
                bh[j][1] = *(const uint32_t*)(sm + OFF_BH + o1);
                bl[j][0] = *(const uint32_t*)(sm + OFF_BL + o0);
                bl[j][1] = *(const uint32_t*)(sm + OFF_BL + o1);
            }
            #pragma unroll
            for (int i = 0; i < 4; i++)
                #pragma unroll
                for (int j = 0; j < 2; j++) {
                    MMA16816(acc[i][j], ah[i], bh[j]);
                    MMA16816(acc[i][j], ah[i], bl[j]);
                    MMA16816(acc[i][j], al[i], bh[j]);
                }
        }
    }
}

// ---------------------------------------------------------------------------
// qkv GEMM + fused RMSNorm/split epilogue. grid (12, 16), 256 threads.
// ---------------------------------------------------------------------------
__global__ void __launch_bounds__(256) qkv_mma(const float* __restrict__ x,
                                               const float* __restrict__ w_qkv,
                                               const float* __restrict__ qn_w,
                                               const float* __restrict__ kn_w)
{
    __shared__ __align__(16) unsigned char sm[49152];
    const int m0 = blockIdx.y * 128, n0 = blockIdx.x * 64;
    float acc[4][2][4] = {};

    mma_nt_256(sm, x, w_qkv, m0, n0, acc);

    const int tid = threadIdx.x;
    const int wid = tid >> 5, lane = tid & 31;
    const int wm = wid & 1, wn = wid >> 1;
    const int g = lane >> 2, tg = lane & 3;

    const int third = blockIdx.x >> 2;                 // 0=q, 1=k, 2=v
    const int hb = (blockIdx.x & 3) * 32 + wn * 8 + tg;

    if (third == 0) {
        const float L2 = 1.02013946f;                  // log2(e)/sqrt(2)
        const float w0 = qn_w[0] * L2, w1 = qn_w[1] * L2;
        #pragma unroll
        for (int i = 0; i < 4; i++)
            #pragma unroll
            for (int j = 0; j < 2; j++) {
                int h = hb + j * 4;
                #pragma unroll
                for (int hf = 0; hf < 2; hf++) {
                    int m = m0 + wm * 64 + i * 16 + g + hf * 8;
                    float qx = acc[i][j][2 * hf], qy = acc[i][j][2 * hf + 1];
                    float r = rsqrtf(0.5f * (qx * qx + qy * qy) + 1e-6f);
                    g_q[((size_t)((m >> 10) * HH + h)) * TT + (m & 1023)] =
                        make_float2(qx * r * w0, qy * r * w1);
                }
            }
    } else if (third == 1) {
        const float w0 = kn_w[0], w1 = kn_w[1];
        #pragma unroll
        for (int i = 0; i < 4; i++)
            #pragma unroll
            for (int j = 0; j < 2; j++) {
                int h = hb + j * 4;
                #pragma unroll
                for (int hf = 0; hf < 2; hf++) {
                    int m = m0 + wm * 64 + i * 16 + g + hf * 8;
                    float kx = acc[i][j][2 * hf], ky = acc[i][j][2 * hf + 1];
                    float r = rsqrtf(0.5f * (kx * kx + ky * ky) + 1e-6f);
                    size_t o = ((size_t)((m >> 10) * HH + h)) * TT + (m & 1023);
                    g_kx[o] = kx * r * w0;
                    g_ky[o] = ky * r * w1;
                }
            }
    } else {
        #pragma unroll
        for (int i = 0; i < 4; i++)
            #pragma unroll
            for (int j = 0; j < 2; j++) {
                int h = hb + j * 4;
                #pragma unroll
                for (int hf = 0; hf < 2; hf++) {
                    int m = m0 + wm * 64 + i * 16 + g + hf * 8;
                    size_t o = ((size_t)((m >> 10) * HH + h)) * TT + (m & 1023);
                    g_vx[o] = acc[i][j][2 * hf];
                    g_vy[o] = acc[i][j][2 * hf + 1];
                }
            }
    }
}

// ---------------------------------------------------------------------------
// proj GEMM. grid (4, 16), 256 threads.
// ---------------------------------------------------------------------------
__global__ void __launch_bounds__(256) proj_mma(const float* __restrict__ y,
                                                const float* __restrict__ w_proj,
                                                float* __restrict__ out)
{
    __shared__ __align__(16) unsigned char sm[49152];
    const int m0 = blockIdx.y * 128, n0 = blockIdx.x * 64;
    float acc[4][2][4] = {};

    mma_nt_256(sm, y, w_proj, m0, n0, acc);

    const int tid = threadIdx.x;
    const int wid = tid >> 5, lane = tid & 31;
    const int wm = wid & 1, wn = wid >> 1;
    const int g = lane >> 2, tg = lane & 3;

    #pragma unroll
    for (int i = 0; i < 4; i++)
        #pragma unroll
        for (int j = 0; j < 2; j++) {
            int n = n0 + wn * 16 + j * 8 + 2 * tg;
            #pragma unroll
            for (int hf = 0; hf < 2; hf++) {
                int m = m0 + wm * 64 + i * 16 + g + hf * 8;
                *(float2*)(out + (size_t)m * CC + n) =
                    make_float2(acc[i][j][2 * hf], acc[i][j][2 * hf + 1]);
            }
        }
}

// ---------------------------------------------------------------------------
// Fused Fourier attention (R8, unchanged). One 128-thread block per (b,h).
// ---------------------------------------------------------------------------
__global__ void __launch_bounds__(128) fourier_attn()
{
    __shared__ float  sPsi[NFF][132];
    __shared__ float  svx[128], svy[128];
    __shared__ float  sG[NCH2][NCHF];
    __shared__ float4 skv[TT];
    const int bh = blockIdx.x, tid = threadIdx.x;
    const int warp = tid >> 5, lane = tid & 31;
    const size_t base = (size_t)bh * TT;

    for (int it = 0; it < 8; it++) {
        int s = it * 128 + tid;
        float kx = g_kx[base + s], ky = g_ky[base + s];
        float vx = g_vx[base + s], vy = g_vy[base + s];
        __syncthreads();
        skv[s] = make_float4(kx, ky, vx, vy);
        svx[tid] = vx; svy[tid] = vy;
        float cb = kx * 0.70710678f, sb = ky * 0.70710678f;
        float c2b = cb + cb;
        sPsi[0][tid] = 1.0f;
        sPsi[1][tid] = cb;
        sPsi[2][tid] = sb;
        float cp = 1.0f, sp = 0.0f, cc = cb, cs = sb;
        #pragma unroll
        for (int m = 2; m <= 8; m++) {
            float cn = fmaf(c2b, cc, -cp);
            float sn = fmaf(c2b, cs, -sp);
            sPsi[2 * m - 1][tid] = cn;
            sPsi[2 * m][tid]     = sn;
            cp = cc; sp = cs; cc = cn; cs = sn;
        }
        __syncthreads();
        for (int task = tid; task < 4 * NCHF; task += 128) {
            int lc = task / NCHF;
            int ch = task - lc * NCHF;
            int f  = ch / 3, w = ch - 3 * f;
            const float4* pp4 = (const float4*)&sPsi[f][lc * 32];
            float acc = 0.0f;
            if (w == 0) {
                #pragma unroll
                for (int j = 0; j < 8; j++) {
                    float4 v = pp4[j];
                    acc += (v.x + v.y) + (v.z + v.w);
                }
            } else {
                const float4* wp4 = (const float4*)((w == 1 ? svx : svy) + lc * 32);
                #pragma unroll
                for (int j = 0; j < 8; j++) {
                    float4 v = pp4[j], u = wp4[j];
                    acc = fmaf(v.x, u.x, acc); acc = fmaf(v.y, u.y, acc);
                    acc = fmaf(v.z, u.z, acc); acc = fmaf(v.w, u.w, acc);
                }
            }
            sG[it * 4 + lc][ch] = acc;
        }
    }
    __syncthreads();

    if (tid < NCHF) {
        float coef = c_CM[tid / 3];
        float excl = 0.0f;
        #pragma unroll
        for (int c = 0; c < NCH2; c++) {
            float v = sG[c][tid];
            sG[c][tid] = excl * coef;
            excl += v;
        }
    }
    __syncthreads();

    const int b = bh >> 7, h = bh & 127;
    for (int it = 0; it < 8; it++) {
        int t = it * 128 + tid;
        float2 q = g_q[base + t];

        const float4* kp = &skv[(it * 4 + warp) << 5];
        float num0 = 0.f, num1 = 0.f, den = 0.f;

        int n = lane + 1, n4 = n & ~3;
        int s = 0;
        for (; s < n4; s += 4) {
            #pragma unroll
            for (int j = 0; j < 4; j++) {
                float4 kv = kp[s + j];
                float p = ex2f(fmaf(q.x, kv.x, q.y * kv.y));
                num0 = fmaf(p, kv.z, num0);
                num1 = fmaf(p, kv.w, num1);
                den += p;
            }
        }
        for (; s < n; s++) {
            float4 kv = kp[s];
            float p = ex2f(fmaf(q.x, kv.x, q.y * kv.y));
            num0 = fmaf(p, kv.z, num0);
            num1 = fmaf(p, kv.w, num1);
            den += p;
        }

        const float* S = sG[it * 4 + warp];
        float ca = q.x * 0.69314718f, sa = q.y * 0.69314718f;
        den  += S[0];
        num0 += S[1];
        num1 += S[2];
        float c2a = ca + ca;
        float cp = 1.f, sp = 0.f, cc = ca, cs = sa;
        #pragma unroll
        for (int m = 1; m <= 8; m++) {
            int b3 = 3 * (2 * m - 1);
            den  = fmaf(cc, S[b3 + 0], den);
            num0 = fmaf(cc, S[b3 + 1], num0);
            num1 = fmaf(cc, S[b3 + 2], num1);
            den  = fmaf(cs, S[b3 + 3], den);
            num0 = fmaf(cs, S[b3 + 4], num0);
            num1 = fmaf(cs, S[b3 + 5], num1);
            float cn = fmaf(c2a, cc, -cp);
            float sn = fmaf(c2a, cs, -sp);
            cp = cc; sp = cs; cc = cn; cs = sn;
        }

        float inv = 1.0f / den;
        float* yp = g_y + (size_t)(b * TT + t) * CC + 2 * h;
        yp[0] = num0 * inv;
        yp[1] = num1 * inv;
    }
}

// ---------------------------------------------------------------------------
extern "C" void kernel_launch(void* const* d_in, const int* in_sizes, int n_in,
                              void* d_out, int out_size)
{
    const float* x      = (const float*)d_in[0];   // (2,1024,256)
    const float* w_qkv  = (const float*)d_in[1];   // (768,256)
    const float* w_proj = (const float*)d_in[2];   // (256,256)
    const float* qn_w   = (const float*)d_in[3];   // (2,)
    const float* kn_w   = (const float*)d_in[4];   // (2,)
    float* out = (float*)d_out;                    // (2,1024,256)

    float* y_p;
    cudaGetSymbolAddress((void**)&y_p, g_y);

    // qkv = x @ w_qkv^T with fused rmsnorm/split epilogue -> g_q/g_kx/...
    qkv_mma<<<dim3(12, 16), 256>>>(x, w_qkv, qn_w, kn_w);
    // fused Fourier attention -> g_y
    fourier_attn<<<NBH, 128>>>();
    // out = y @ w_proj^T
    proj_mma<<<dim3(4, 16), 256>>>(y_p, w_proj, out);
}

// round 13
// speedup vs baseline: 2.6961x; 1.0708x over previous
#include <cuda_runtime.h>
#include <cuda_bf16.h>
#include <cstdint>
#include <cstddef>

// Problem constants: B=2, T=1024, C=256, head_dim=2, H=128
#define BB 2
#define TT 1024
#define CC 256
#define HH 128
#define NBH (BB*HH)      // 256
#define NCH2 32          // 32-chunks for intra-exact attention
#define NFF 17           // Fourier features: 1, {cos,sin}(m*beta) m=1..8
#define NCHF (NFF*3)     // 51 channels

// Scratch (no allocations allowed -> __device__ globals)
__device__ float2 g_q  [NBH * TT];
__device__ float  g_kx [NBH * TT];
__device__ float  g_ky [NBH * TT];
__device__ float  g_vx [NBH * TT];
__device__ float  g_vy [NBH * TT];
// bf16 hi/lo pre-split operands
__device__ __nv_bfloat162 g_xh[BB*TT*CC/2],  g_xl[BB*TT*CC/2];    // x
__device__ __nv_bfloat162 g_wh[3*CC*CC/2],   g_wl[3*CC*CC/2];     // w_qkv
__device__ __nv_bfloat162 g_ph[CC*CC/2],     g_pl[CC*CC/2];       // w_proj
__device__ __nv_bfloat162 g_yh[BB*TT*CC/2],  g_yl[BB*TT*CC/2];    // attn out

// Fourier coefficients: C0=I0(sqrt2), Cm=2*Im(sqrt2)
__constant__ float c_CM[NFF] = {
    1.56608293f,
    1.79848892f, 1.79848892f,
    0.58871897f, 0.58871897f,
    0.13333993f, 0.13333993f,
    0.02300557f, 0.02300557f,
    3.2007638e-3f, 3.2007638e-3f,
    3.7280500e-4f, 3.7280500e-4f,
    3.7328000e-5f, 3.7328000e-5f,
    3.2767400e-6f, 3.2767400e-6f
};

__device__ __forceinline__ float ex2f(float x) {
    float r; asm("ex2.approx.f32 %0, %1;" : "=f"(r) : "f"(x)); return r;
}
__device__ __forceinline__ uint32_t smem_u32(const void* p) {
    uint32_t a;
    asm("{ .reg .u64 t; cvta.to.shared.u64 t, %1; cvt.u32.u64 %0, t; }"
        : "=r"(a) : "l"(p));
    return a;
}

// Portable Ampere-style bf16 MMA (valid PTX for plain sm_103 target)
#define MMA16816(c, a, b) \
    asm volatile("mma.sync.aligned.m16n8k16.row.col.f32.bf16.bf16.f32 " \
        "{%0,%1,%2,%3}, {%4,%5,%6,%7}, {%8,%9}, {%0,%1,%2,%3};" \
        : "+f"((c)[0]), "+f"((c)[1]), "+f"((c)[2]), "+f"((c)[3]) \
        : "r"((a)[0]), "r"((a)[1]), "r"((a)[2]), "r"((a)[3]), \
          "r"((b)[0]), "r"((b)[1]))

// cp.async (portable sm_80+)
#define CP_ASYNC16(dst, src) \
    asm volatile("cp.async.ca.shared.global [%0], [%1], 16;" \
                 :: "r"(dst), "l"(src) : "memory")
#define CP_COMMIT() asm volatile("cp.async.commit_group;" ::: "memory")
#define CP_WAIT0()  asm volatile("cp.async.wait_group 0;" ::: "memory")

// Shared tile geometry: bf16 [rows][64] with XOR swizzle on bits 4-6.
__device__ __forceinline__ int swzb(int row, int colbyte) {
    return row * 128 + (colbyte ^ ((row & 7) << 4));
}

// smem layout (48KB exactly, static)
#define OFF_AH 0
#define OFF_AL 16384
#define OFF_BH 32768
#define OFF_BL 40960

// ---------------------------------------------------------------------------
// fp32 -> bf16 hi/lo split (2 elements/thread)
// ---------------------------------------------------------------------------
__global__ void __launch_bounds__(256) convert_split(const float* __restrict__ src,
                                                     __nv_bfloat162* __restrict__ hi,
                                                     __nv_bfloat162* __restrict__ lo,
                                                     int n2)
{
    int i = blockIdx.x * blockDim.x + threadIdx.x;
    if (i >= n2) return;
    float2 v = ((const float2*)src)[i];
    __nv_bfloat162 h = __floats2bfloat162_rn(v.x, v.y);
    float hx = __bfloat162float(h.x), hy = __bfloat162float(h.y);
    __nv_bfloat162 l = __floats2bfloat162_rn(v.x - hx, v.y - hy);
    hi[i] = h;
    lo[i] = l;
}

// ---------------------------------------------------------------------------
// Mainloop: acc += A[m0..+127][0..255] * B[n0..+63][0..255]^T, operands
// pre-split bf16 hi/lo in global. cp.async 16B into swizzled smem tiles.
// 256 threads, 8 warps as 2(m) x 4(n).
// ---------------------------------------------------------------------------
__device__ __forceinline__ void mma_nt_bf16(unsigned char* sm,
                                            const __nv_bfloat16* __restrict__ Ah,
                                            const __nv_bfloat16* __restrict__ Al,
                                            const __nv_bfloat16* __restrict__ Bh,
                                            const __nv_bfloat16* __restrict__ Bl,
                                            int m0, int n0,
                                            float acc[4][2][4])
{
    const int tid = threadIdx.x;
    const int wid = tid >> 5, lane = tid & 31;
    const int wm = wid & 1, wn = wid >> 1;
    const int g = lane >> 2, tg = lane & 3;
    const uint32_t smb = smem_u32(sm);

    for (int ci = 0; ci < 4; ci++) {
        const int k0 = ci * 64;
        __syncthreads();                 // previous chunk fully consumed
        #pragma unroll
        for (int it = 0; it < 12; it++) {
            int p = it * 256 + tid;
            const __nv_bfloat16* src;
            uint32_t dst;
            if (p < 2048) {              // A tiles: 128 rows x 16 segs (8 hi, 8 lo)
                int row = p >> 4, u = p & 15, seg = u & 7;
                src = ((u < 8) ? Ah : Al) + (size_t)(m0 + row) * 256 + k0 + seg * 8;
                dst = smb + ((u < 8) ? OFF_AH : OFF_AL) + swzb(row, seg * 16);
            } else {                     // B tiles: 64 rows x 16 segs
                int q = p - 2048;
                int row = q >> 4, u = q & 15, seg = u & 7;
                src = ((u < 8) ? Bh : Bl) + (size_t)(n0 + row) * 256 + k0 + seg * 8;
                dst = smb + ((u < 8) ? OFF_BH : OFF_BL) + swzb(row, seg * 16);
            }
            CP_ASYNC16(dst, src);
        }
        CP_COMMIT();
        CP_WAIT0();
        __syncthreads();

        #pragma unroll
        for (int ks = 0; ks < 4; ks++) {
            const int cb = ks * 32 + tg * 4;
            uint32_t ah[4][4], al[4][4], bh[2][2], bl[2][2];
            #pragma unroll
            for (int i = 0; i < 4; i++) {
                int r = wm * 64 + i * 16 + g;
                int o00 = swzb(r, cb), o10 = swzb(r + 8, cb);
                int o01 = swzb(r, cb + 16), o11 = swzb(r + 8, cb + 16);
                ah[i][0] = *(const uint32_t*)(sm + OFF_AH + o00);
                ah[i][1] = *(const uint32_t*)(sm + OFF_AH + o10);
                ah[i][2] = *(const uint32_t*)(sm + OFF_AH + o01);
                ah[i][3] = *(const uint32_t*)(sm + OFF_AH + o11);
                al[i][0] = *(const uint32_t*)(sm + OFF_AL + o00);
                al[i][1] = *(const uint32_t*)(sm + OFF_AL + o10);
                al[i][2] = *(const uint32_t*)(sm + OFF_AL + o01);
                al[i][3] = *(const uint32_t*)(sm + OFF_AL + o11);
            }
            #pragma unroll
            for (int j = 0; j < 2; j++) {
                int rn = wn * 16 + j * 8 + g;
                int o0 = swzb(rn, cb), o1 = swzb(rn, cb + 16);
                bh[j][0] = *(const uint32_t*)(sm + OFF_BH + o0);
                bh[j][1] = *(const uint32_t*)(sm + OFF_BH + o1);
                bl[j][0] = *(const uint32_t*)(sm + OFF_BL + o0);
                bl[j][1] = *(const uint32_t*)(sm + OFF_BL + o1);
            }
            #pragma unroll
            for (int i = 0; i < 4; i++)
                #pragma unroll
                for (int j = 0; j < 2; j++) {
                    MMA16816(acc[i][j], ah[i], bh[j]);
                    MMA16816(acc[i][j], ah[i], bl[j]);
                    MMA16816(acc[i][j], al[i], bh[j]);
                }
        }
    }
}

// ---------------------------------------------------------------------------
// qkv GEMM + fused RMSNorm/split epilogue. grid (12, 16), 256 threads.
// ---------------------------------------------------------------------------
__global__ void __launch_bounds__(256) qkv_mma(const float* __restrict__ qn_w,
                                               const float* __restrict__ kn_w)
{
    __shared__ __align__(16) unsigned char sm[49152];
    const int m0 = blockIdx.y * 128, n0 = blockIdx.x * 64;
    float acc[4][2][4] = {};

    mma_nt_bf16(sm, (const __nv_bfloat16*)g_xh, (const __nv_bfloat16*)g_xl,
                    (const __nv_bfloat16*)g_wh, (const __nv_bfloat16*)g_wl,
                m0, n0, acc);

    const int tid = threadIdx.x;
    const int wid = tid >> 5, lane = tid & 31;
    const int wm = wid & 1, wn = wid >> 1;
    const int g = lane >> 2, tg = lane & 3;

    const int third = blockIdx.x >> 2;                 // 0=q, 1=k, 2=v
    const int hb = (blockIdx.x & 3) * 32 + wn * 8 + tg;

    if (third == 0) {
        const float L2 = 1.02013946f;                  // log2(e)/sqrt(2)
        const float w0 = qn_w[0] * L2, w1 = qn_w[1] * L2;
        #pragma unroll
        for (int i = 0; i < 4; i++)
            #pragma unroll
            for (int j = 0; j < 2; j++) {
                int h = hb + j * 4;
                #pragma unroll
                for (int hf = 0; hf < 2; hf++) {
                    int m = m0 + wm * 64 + i * 16 + g + hf * 8;
                    float qx = acc[i][j][2 * hf], qy = acc[i][j][2 * hf + 1];
                    float r = rsqrtf(0.5f * (qx * qx + qy * qy) + 1e-6f);
                    g_q[((size_t)((m >> 10) * HH + h)) * TT + (m & 1023)] =
                        make_float2(qx * r * w0, qy * r * w1);
                }
            }
    } else if (third == 1) {
        const float w0 = kn_w[0], w1 = kn_w[1];
        #pragma unroll
        for (int i = 0; i < 4; i++)
            #pragma unroll
            for (int j = 0; j < 2; j++) {
                int h = hb + j * 4;
                #pragma unroll
                for (int hf = 0; hf < 2; hf++) {
                    int m = m0 + wm * 64 + i * 16 + g + hf * 8;
                    float kx = acc[i][j][2 * hf], ky = acc[i][j][2 * hf + 1];
                    float r = rsqrtf(0.5f * (kx * kx + ky * ky) + 1e-6f);
                    size_t o = ((size_t)((m >> 10) * HH + h)) * TT + (m & 1023);
                    g_kx[o] = kx * r * w0;
                    g_ky[o] = ky * r * w1;
                }
            }
    } else {
        #pragma unroll
        for (int i = 0; i < 4; i++)
            #pragma unroll
            for (int j = 0; j < 2; j++) {
                int h = hb + j * 4;
                #pragma unroll
                for (int hf = 0; hf < 2; hf++) {
                    int m = m0 + wm * 64 + i * 16 + g + hf * 8;
                    size_t o = ((size_t)((m >> 10) * HH + h)) * TT + (m & 1023);
                    g_vx[o] = acc[i][j][2 * hf];
                    g_vy[o] = acc[i][j][2 * hf + 1];
                }
            }
    }
}

// ---------------------------------------------------------------------------
// proj GEMM. grid (4, 16), 256 threads.
// ---------------------------------------------------------------------------
__global__ void __launch_bounds__(256) proj_mma(float* __restrict__ out)
{
    __shared__ __align__(16) unsigned char sm[49152];
    const int m0 = blockIdx.y * 128, n0 = blockIdx.x * 64;
    float acc[4][2][4] = {};

    mma_nt_bf16(sm, (const __nv_bfloat16*)g_yh, (const __nv_bfloat16*)g_yl,
                    (const __nv_bfloat16*)g_ph, (const __nv_bfloat16*)g_pl,
                m0, n0, acc);

    const int tid = threadIdx.x;
    const int wid = tid >> 5, lane = tid & 31;
    const int wm = wid & 1, wn = wid >> 1;
    const int g = lane >> 2, tg = lane & 3;

    #pragma unroll
    for (int i = 0; i < 4; i++)
        #pragma unroll
        for (int j = 0; j < 2; j++) {
            int n = n0 + wn * 16 + j * 8 + 2 * tg;
            #pragma unroll
            for (int hf = 0; hf < 2; hf++) {
                int m = m0 + wm * 64 + i * 16 + g + hf * 8;
                *(float2*)(out + (size_t)m * CC + n) =
                    make_float2(acc[i][j][2 * hf], acc[i][j][2 * hf + 1]);
            }
        }
}

// ---------------------------------------------------------------------------
// Fused Fourier attention. One 128-thread block per (b,h).
// Output written as bf16 hi/lo (proj operand) directly.
// ---------------------------------------------------------------------------
__global__ void __launch_bounds__(128) fourier_attn()
{
    __shared__ float  sPsi[NFF][132];
    __shared__ float  svx[128], svy[128];
    __shared__ float  sG[NCH2][NCHF];
    __shared__ float4 skv[TT];
    const int bh = blockIdx.x, tid = threadIdx.x;
    const int warp = tid >> 5, lane = tid & 31;
    const size_t base = (size_t)bh * TT;

    for (int it = 0; it < 8; it++) {
        int s = it * 128 + tid;
        float kx = g_kx[base + s], ky = g_ky[base + s];
        float vx = g_vx[base + s], vy = g_vy[base + s];
        __syncthreads();
        skv[s] = make_float4(kx, ky, vx, vy);
        svx[tid] = vx; svy[tid] = vy;
        float cb = kx * 0.70710678f, sb = ky * 0.70710678f;
        float c2b = cb + cb;
        sPsi[0][tid] = 1.0f;
        sPsi[1][tid] = cb;
        sPsi[2][tid] = sb;
        float cp = 1.0f, sp = 0.0f, cc = cb, cs = sb;
        #pragma unroll
        for (int m = 2; m <= 8; m++) {
            float cn = fmaf(c2b, cc, -cp);
            float sn = fmaf(c2b, cs, -sp);
            sPsi[2 * m - 1][tid] = cn;
            sPsi[2 * m][tid]     = sn;
            cp = cc; sp = cs; cc = cn; cs = sn;
        }
        __syncthreads();
        for (int task = tid; task < 4 * NCHF; task += 128) {
            int lc = task / NCHF;
            int ch = task - lc * NCHF;
            int f  = ch / 3, w = ch - 3 * f;
            const float4* pp4 = (const float4*)&sPsi[f][lc * 32];
            float acc = 0.0f;
            if (w == 0) {
                #pragma unroll
                for (int j = 0; j < 8; j++) {
                    float4 v = pp4[j];
                    acc += (v.x + v.y) + (v.z + v.w);
                }
            } else {
                const float4* wp4 = (const float4*)((w == 1 ? svx : svy) + lc * 32);
                #pragma unroll
                for (int j = 0; j < 8; j++) {
                    float4 v = pp4[j], u = wp4[j];
                    acc = fmaf(v.x, u.x, acc); acc = fmaf(v.y, u.y, acc);
                    acc = fmaf(v.z, u.z, acc); acc = fmaf(v.w, u.w, acc);
                }
            }
            sG[it * 4 + lc][ch] = acc;
        }
    }
    __syncthreads();

    if (tid < NCHF) {
        float coef = c_CM[tid / 3];
        float excl = 0.0f;
        #pragma unroll
        for (int c = 0; c < NCH2; c++) {
            float v = sG[c][tid];
            sG[c][tid] = excl * coef;
            excl += v;
        }
    }
    __syncthreads();

    const int b = bh >> 7, h = bh & 127;
    for (int it = 0; it < 8; it++) {
        int t = it * 128 + tid;
        float2 q = g_q[base + t];

        const float4* kp = &skv[(it * 4 + warp) << 5];
        float num0 = 0.f, num1 = 0.f, den = 0.f;

        int n = lane + 1, n4 = n & ~3;
        int s = 0;
        for (; s < n4; s += 4) {
            #pragma unroll
            for (int j = 0; j < 4; j++) {
                float4 kv = kp[s + j];
                float p = ex2f(fmaf(q.x, kv.x, q.y * kv.y));
                num0 = fmaf(p, kv.z, num0);
                num1 = fmaf(p, kv.w, num1);
                den += p;
            }
        }
        for (; s < n; s++) {
            float4 kv = kp[s];
            float p = ex2f(fmaf(q.x, kv.x, q.y * kv.y));
            num0 = fmaf(p, kv.z, num0);
            num1 = fmaf(p, kv.w, num1);
            den += p;
        }

        const float* S = sG[it * 4 + warp];
        float ca = q.x * 0.69314718f, sa = q.y * 0.69314718f;
        den  += S[0];
        num0 += S[1];
        num1 += S[2];
        float c2a = ca + ca;
        float cp = 1.f, sp = 0.f, cc = ca, cs = sa;
        #pragma unroll
        for (int m = 1; m <= 8; m++) {
            int b3 = 3 * (2 * m - 1);
            den  = fmaf(cc, S[b3 + 0], den);
            num0 = fmaf(cc, S[b3 + 1], num0);
            num1 = fmaf(cc, S[b3 + 2], num1);
            den  = fmaf(cs, S[b3 + 3], den);
            num0 = fmaf(cs, S[b3 + 4], num0);
            num1 = fmaf(cs, S[b3 + 5], num1);
            float cn = fmaf(c2a, cc, -cp);
            float sn = fmaf(c2a, cs, -sp);
            cp = cc; sp = cs; cc = cn; cs = sn;
        }

        float inv = 1.0f / den;
        float o0 = num0 * inv, o1 = num1 * inv;
        // write bf16 hi/lo split directly (proj GEMM operand)
        __nv_bfloat162 h2 = __floats2bfloat162_rn(o0, o1);
        __nv_bfloat162 l2 = __floats2bfloat162_rn(o0 - __bfloat162float(h2.x),
                                                  o1 - __bfloat162float(h2.y));
        size_t yo = ((size_t)(b * TT + t) * CC + 2 * h) >> 1;
        g_yh[yo] = h2;
        g_yl[yo] = l2;
    }
}

// ---------------------------------------------------------------------------
extern "C" void kernel_launch(void* const* d_in, const int* in_sizes, int n_in,
                              void* d_out, int out_size)
{
    const float* x      = (const float*)d_in[0];   // (2,1024,256)
    const float* w_qkv  = (const float*)d_in[1];   // (768,256)
    const float* w_proj = (const float*)d_in[2];   // (256,256)
    const float* qn_w   = (const float*)d_in[3];   // (2,)
    const float* kn_w   = (const float*)d_in[4];   // (2,)
    float* out = (float*)d_out;                    // (2,1024,256)

    __nv_bfloat162 *xh, *xl, *wh, *wl, *ph, *pl;
    cudaGetSymbolAddress((void**)&xh, g_xh); cudaGetSymbolAddress((void**)&xl, g_xl);
    cudaGetSymbolAddress((void**)&wh, g_wh); cudaGetSymbolAddress((void**)&wl, g_wl);
    cudaGetSymbolAddress((void**)&ph, g_ph); cudaGetSymbolAddress((void**)&pl, g_pl);

    // pre-split fp32 -> bf16 hi/lo
    convert_split<<<(BB*TT*CC/2)/256, 256>>>(x, xh, xl, BB*TT*CC/2);
    convert_split<<<(3*CC*CC/2)/256, 256>>>(w_qkv, wh, wl, 3*CC*CC/2);
    convert_split<<<(CC*CC/2)/256, 256>>>(w_proj, ph, pl, CC*CC/2);

    // qkv = x @ w_qkv^T with fused rmsnorm/split epilogue -> g_q/g_kx/...
    qkv_mma<<<dim3(12, 16), 256>>>(qn_w, kn_w);
    // fused Fourier attention -> g_yh/g_yl (bf16 hi/lo)
    fourier_attn<<<NBH, 128>>>();
    // out = y @ w_proj^T
    proj_mma<<<dim3(4, 16), 256>>>(out);
}

// round 16
// speedup vs baseline: 3.1603x; 1.1722x over previous
#include <cuda_runtime.h>
#include <cuda_bf16.h>
#include <cstdint>
#include <cstddef>

// Problem constants: B=2, T=1024, C=256, head_dim=2, H=128
#define BB 2
#define TT 1024
#define CC 256
#define HH 128
#define NBH (BB*HH)      // 256
#define NCH2 32          // 32-chunks for intra-exact attention
#define NFF 17           // Fourier features: 1, {cos,sin}(m*beta) m=1..8
#define NCHF (NFF*3)     // 51 channels

// Scratch (no allocations allowed -> __device__ globals)
__device__ float2 g_q  [NBH * TT];
__device__ float  g_kx [NBH * TT];
__device__ float  g_ky [NBH * TT];
__device__ float  g_vx [NBH * TT];
__device__ float  g_vy [NBH * TT];
// bf16 hi/lo pre-split operands
__device__ __nv_bfloat162 g_xh[BB*TT*CC/2],  g_xl[BB*TT*CC/2];    // x
__device__ __nv_bfloat162 g_wh[3*CC*CC/2],   g_wl[3*CC*CC/2];     // w_qkv
__device__ __nv_bfloat162 g_ph[CC*CC/2],     g_pl[CC*CC/2];       // w_proj
__device__ __nv_bfloat162 g_yh[BB*TT*CC/2],  g_yl[BB*TT*CC/2];    // attn out

// Fourier coefficients: C0=I0(sqrt2), Cm=2*Im(sqrt2)
__constant__ float c_CM[NFF] = {
    1.56608293f,
    1.79848892f, 1.79848892f,
    0.58871897f, 0.58871897f,
    0.13333993f, 0.13333993f,
    0.02300557f, 0.02300557f,
    3.2007638e-3f, 3.2007638e-3f,
    3.7280500e-4f, 3.7280500e-4f,
    3.7328000e-5f, 3.7328000e-5f,
    3.2767400e-6f, 3.2767400e-6f
};

__device__ __forceinline__ float ex2f(float x) {
    float r; asm("ex2.approx.f32 %0, %1;" : "=f"(r) : "f"(x)); return r;
}
__device__ __forceinline__ uint32_t smem_u32(const void* p) {
    uint32_t a;
    asm("{ .reg .u64 t; cvta.to.shared.u64 t, %1; cvt.u32.u64 %0, t; }"
        : "=r"(a) : "l"(p));
    return a;
}

// Portable Ampere-style bf16 MMA (valid PTX for plain sm_103 target)
#define MMA16816(c, a, b) \
    asm volatile("mma.sync.aligned.m16n8k16.row.col.f32.bf16.bf16.f32 " \
        "{%0,%1,%2,%3}, {%4,%5,%6,%7}, {%8,%9}, {%0,%1,%2,%3};" \
        : "+f"((c)[0]), "+f"((c)[1]), "+f"((c)[2]), "+f"((c)[3]) \
        : "r"((a)[0]), "r"((a)[1]), "r"((a)[2]), "r"((a)[3]), \
          "r"((b)[0]), "r"((b)[1]))

// cp.async (portable sm_80+)
#define CP_ASYNC16(dst, src) \
    asm volatile("cp.async.ca.shared.global [%0], [%1], 16;" \
                 :: "r"(dst), "l"(src) : "memory")
#define CP_COMMIT() asm volatile("cp.async.commit_group;" ::: "memory")
#define CP_WAIT0()  asm volatile("cp.async.wait_group 0;" ::: "memory")
#define CP_WAIT1()  asm volatile("cp.async.wait_group 1;" ::: "memory")

// Shared tile geometry: bf16 [rows][64] with XOR swizzle on bits 4-6.
__device__ __forceinline__ int swzb(int row, int colbyte) {
    return row * 128 + (colbyte ^ ((row & 7) << 4));
}

// Per-stage smem layout (32KB/stage, 2 stages = 64KB dynamic)
#define ST_AH 0
#define ST_AL 8192
#define ST_BH 16384
#define ST_BL 24576
#define ST_SIZE 32768
#define SM_DYN 65536

// ---------------------------------------------------------------------------
// fp32 -> bf16 hi/lo split (2 elements/thread)
// ---------------------------------------------------------------------------
__global__ void __launch_bounds__(256) convert_split(const float* __restrict__ src,
                                                     __nv_bfloat162* __restrict__ hi,
                                                     __nv_bfloat162* __restrict__ lo,
                                                     int n2)
{
    int i = blockIdx.x * blockDim.x + threadIdx.x;
    if (i >= n2) return;
    float2 v = ((const float2*)src)[i];
    __nv_bfloat162 h = __floats2bfloat162_rn(v.x, v.y);
    float hx = __bfloat162float(h.x), hy = __bfloat162float(h.y);
    __nv_bfloat162 l = __floats2bfloat162_rn(v.x - hx, v.y - hy);
    hi[i] = h;
    lo[i] = l;
}

// ---------------------------------------------------------------------------
// Issue cp.async loads for one 64-wide K chunk (A: 64 rows, B: 64 rows).
// 2048 x 16B ops across 256 threads = 8 per thread.
// ---------------------------------------------------------------------------
__device__ __forceinline__ void issue_chunk(uint32_t smb, int st,
                                            const __nv_bfloat16* __restrict__ Ah,
                                            const __nv_bfloat16* __restrict__ Al,
                                            const __nv_bfloat16* __restrict__ Bh,
                                            const __nv_bfloat16* __restrict__ Bl,
                                            int m0, int n0, int k0, int tid)
{
    const uint32_t sb = smb + st * ST_SIZE;
    #pragma unroll
    for (int it = 0; it < 8; it++) {
        int p = it * 256 + tid;
        const __nv_bfloat16* src;
        uint32_t dst;
        if (p < 1024) {                  // A: 64 rows x 16 segs (8 hi, 8 lo)
            int row = p >> 4, u = p & 15, seg = u & 7;
            src = ((u < 8) ? Ah : Al) + (size_t)(m0 + row) * 256 + k0 + seg * 8;
            dst = sb + ((u < 8) ? ST_AH : ST_AL) + swzb(row, seg * 16);
        } else {                         // B: 64 rows x 16 segs
            int q = p - 1024;
            int row = q >> 4, u = q & 15, seg = u & 7;
            src = ((u < 8) ? Bh : Bl) + (size_t)(n0 + row) * 256 + k0 + seg * 8;
            dst = sb + ((u < 8) ? ST_BH : ST_BL) + swzb(row, seg * 16);
        }
        CP_ASYNC16(dst, src);
    }
    CP_COMMIT();
}

// ---------------------------------------------------------------------------
// Compute one K chunk from smem stage st. 64x64 CTA tile, warps 2(m) x 4(n).
// ---------------------------------------------------------------------------
__device__ __forceinline__ void compute_chunk(const unsigned char* sm, int st,
                                              int wm, int wn, int g, int tg,
                                              float acc[2][2][4])
{
    const unsigned char* s = sm + st * ST_SIZE;
    #pragma unroll
    for (int ks = 0; ks < 4; ks++) {
        const int cb = ks * 32 + tg * 4;
        uint32_t ah[2][4], al[2][4], bh[2][2], bl[2][2];
        #pragma unroll
        for (int i = 0; i < 2; i++) {
            int r = wm * 32 + i * 16 + g;
            int o00 = swzb(r, cb), o10 = swzb(r + 8, cb);
            int o01 = swzb(r, cb + 16), o11 = swzb(r + 8, cb + 16);
            ah[i][0] = *(const uint32_t*)(s + ST_AH + o00);
            ah[i][1] = *(const uint32_t*)(s + ST_AH + o10);
            ah[i][2] = *(const uint32_t*)(s + ST_AH + o01);
            ah[i][3] = *(const uint32_t*)(s + ST_AH + o11);
            al[i][0] = *(const uint32_t*)(s + ST_AL + o00);
            al[i][1] = *(const uint32_t*)(s + ST_AL + o10);
            al[i][2] = *(const uint32_t*)(s + ST_AL + o01);
            al[i][3] = *(const uint32_t*)(s + ST_AL + o11);
        }
        #pragma unroll
        for (int j = 0; j < 2; j++) {
            int rn = wn * 16 + j * 8 + g;
            int o0 = swzb(rn, cb), o1 = swzb(rn, cb + 16);
            bh[j][0] = *(const uint32_t*)(s + ST_BH + o0);
            bh[j][1] = *(const uint32_t*)(s + ST_BH + o1);
            bl[j][0] = *(const uint32_t*)(s + ST_BL + o0);
            bl[j][1] = *(const uint32_t*)(s + ST_BL + o1);
        }
        #pragma unroll
        for (int i = 0; i < 2; i++)
            #pragma unroll
            for (int j = 0; j < 2; j++) {
                MMA16816(acc[i][j], ah[i], bh[j]);
                MMA16816(acc[i][j], ah[i], bl[j]);
                MMA16816(acc[i][j], al[i], bh[j]);
            }
    }
}

// Double-buffered mainloop over K=256 in 4 chunks.
__device__ __forceinline__ void mma_nt_pipe(unsigned char* sm,
                                            const __nv_bfloat16* Ah, const __nv_bfloat16* Al,
                                            const __nv_bfloat16* Bh, const __nv_bfloat16* Bl,
                                            int m0, int n0,
                                            int wm, int wn, int g, int tg,
                                            float acc[2][2][4])
{
    const int tid = threadIdx.x;
    const uint32_t smb = smem_u32(sm);

    issue_chunk(smb, 0, Ah, Al, Bh, Bl, m0, n0, 0, tid);
    issue_chunk(smb, 1, Ah, Al, Bh, Bl, m0, n0, 64, tid);
    #pragma unroll
    for (int ci = 0; ci < 4; ci++) {
        if (ci < 3) CP_WAIT1(); else CP_WAIT0();
        __syncthreads();
        compute_chunk(sm, ci & 1, wm, wn, g, tg, acc);
        if (ci + 2 < 4) {
            __syncthreads();       // all warps done reading stage ci&1
            issue_chunk(smb, ci & 1, Ah, Al, Bh, Bl, m0, n0, (ci + 2) * 64, tid);
        }
    }
}

// ---------------------------------------------------------------------------
// qkv GEMM + fused RMSNorm/split epilogue. grid (12, 32), 256 threads.
// ---------------------------------------------------------------------------
__global__ void __launch_bounds__(256) qkv_mma(const float* __restrict__ qn_w,
                                               const float* __restrict__ kn_w)
{
    extern __shared__ __align__(16) unsigned char sm[];
    const int m0 = blockIdx.y * 64, n0 = blockIdx.x * 64;
    const int tid = threadIdx.x;
    const int wid = tid >> 5, lane = tid & 31;
    const int wm = wid & 1, wn = wid >> 1;
    const int g = lane >> 2, tg = lane & 3;
    float acc[2][2][4] = {};

    mma_nt_pipe(sm, (const __nv_bfloat16*)g_xh, (const __nv_bfloat16*)g_xl,
                    (const __nv_bfloat16*)g_wh, (const __nv_bfloat16*)g_wl,
                m0, n0, wm, wn, g, tg, acc);

    const int third = blockIdx.x >> 2;                 // 0=q, 1=k, 2=v
    const int hb = (blockIdx.x & 3) * 32 + wn * 8 + tg;

    if (third == 0) {
        const float L2 = 1.02013946f;                  // log2(e)/sqrt(2)
        const float w0 = qn_w[0] * L2, w1 = qn_w[1] * L2;
        #pragma unroll
        for (int i = 0; i < 2; i++)
            #pragma unroll
            for (int j = 0; j < 2; j++) {
                int h = hb + j * 4;
                #pragma unroll
                for (int hf = 0; hf < 2; hf++) {
                    int m = m0 + wm * 32 + i * 16 + g + hf * 8;
                    float qx = acc[i][j][2 * hf], qy = acc[i][j][2 * hf + 1];
                    float r = rsqrtf(0.5f * (qx * qx + qy * qy) + 1e-6f);
                    g_q[((size_t)((m >> 10) * HH + h)) * TT + (m & 1023)] =
                        make_float2(qx * r * w0, qy * r * w1);
                }
            }
    } else if (third == 1) {
        const float w0 = kn_w[0], w1 = kn_w[1];
        #pragma unroll
        for (int i = 0; i < 2; i++)
            #pragma unroll
            for (int j = 0; j < 2; j++) {
                int h = hb + j * 4;
                #pragma unroll
                for (int hf = 0; hf < 2; hf++) {
                    int m = m0 + wm * 32 + i * 16 + g + hf * 8;
                    float kx = acc[i][j][2 * hf], ky = acc[i][j][2 * hf + 1];
                    float r = rsqrtf(0.5f * (kx * kx + ky * ky) + 1e-6f);
                    size_t o = ((size_t)((m >> 10) * HH + h)) * TT + (m & 1023);
                    g_kx[o] = kx * r * w0;
                    g_ky[o] = ky * r * w1;
                }
            }
    } else {
        #pragma unroll
        for (int i = 0; i < 2; i++)
            #pragma unroll
            for (int j = 0; j < 2; j++) {
                int h = hb + j * 4;
                #pragma unroll
                for (int hf = 0; hf < 2; hf++) {
                    int m = m0 + wm * 32 + i * 16 + g + hf * 8;
                    size_t o = ((size_t)((m >> 10) * HH + h)) * TT + (m & 1023);
                    g_vx[o] = acc[i][j][2 * hf];
                    g_vy[o] = acc[i][j][2 * hf + 1];
                }
            }
    }
}

// ---------------------------------------------------------------------------
// proj GEMM. grid (4, 32), 256 threads.
// ---------------------------------------------------------------------------
__global__ void __launch_bounds__(256) proj_mma(float* __restrict__ out)
{
    extern __shared__ __align__(16) unsigned char sm[];
    const int m0 = blockIdx.y * 64, n0 = blockIdx.x * 64;
    const int tid = threadIdx.x;
    const int wid = tid >> 5, lane = tid & 31;
    const int wm = wid & 1, wn = wid >> 1;
    const int g = lane >> 2, tg = lane & 3;
    float acc[2][2][4] = {};

    mma_nt_pipe(sm, (const __nv_bfloat16*)g_yh, (const __nv_bfloat16*)g_yl,
                    (const __nv_bfloat16*)g_ph, (const __nv_bfloat16*)g_pl,
                m0, n0, wm, wn, g, tg, acc);

    #pragma unroll
    for (int i = 0; i < 2; i++)
        #pragma unroll
        for (int j = 0; j < 2; j++) {
            int n = n0 + wn * 16 + j * 8 + 2 * tg;
            #pragma unroll
            for (int hf = 0; hf < 2; hf++) {
                int m = m0 + wm * 32 + i * 16 + g + hf * 8;
                *(float2*)(out + (size_t)m * CC + n) =
                    make_float2(acc[i][j][2 * hf], acc[i][j][2 * hf + 1]);
            }
        }
}

// ---------------------------------------------------------------------------
// Fused Fourier attention (unchanged). One 128-thread block per (b,h).
// ---------------------------------------------------------------------------
__global__ void __launch_bounds__(128) fourier_attn()
{
    __shared__ float  sPsi[NFF][132];
    __shared__ float  svx[128], svy[128];
    __shared__ float  sG[NCH2][NCHF];
    __shared__ float4 skv[TT];
    const int bh = blockIdx.x, tid = threadIdx.x;
    const int warp = tid >> 5, lane = tid & 31;
    const size_t base = (size_t)bh * TT;

    for (int it = 0; it < 8; it++) {
        int s = it * 128 + tid;
        float kx = g_kx[base + s], ky = g_ky[base + s];
        float vx = g_vx[base + s], vy = g_vy[base + s];
        __syncthreads();
        skv[s] = make_float4(kx, ky, vx, vy);
        svx[tid] = vx; svy[tid] = vy;
        float cb = kx * 0.70710678f, sb = ky * 0.70710678f;
        float c2b = cb + cb;
        sPsi[0][tid] = 1.0f;
        sPsi[1][tid] = cb;
        sPsi[2][tid] = sb;
        float cp = 1.0f, sp = 0.0f, cc = cb, cs = sb;
        #pragma unroll
        for (int m = 2; m <= 8; m++) {
            float cn = fmaf(c2b, cc, -cp);
            float sn = fmaf(c2b, cs, -sp);
            sPsi[2 * m - 1][tid] = cn;
            sPsi[2 * m][tid]     = sn;
            cp = cc; sp = cs; cc = cn; cs = sn;
        }
        __syncthreads();
        for (int task = tid; task < 4 * NCHF; task += 128) {
            int lc = task / NCHF;
            int ch = task - lc * NCHF;
            int f  = ch / 3, w = ch - 3 * f;
            const float4* pp4 = (const float4*)&sPsi[f][lc * 32];
            float acc = 0.0f;
            if (w == 0) {
                #pragma unroll
                for (int j = 0; j < 8; j++) {
                    float4 v = pp4[j];
                    acc += (v.x + v.y) + (v.z + v.w);
                }
            } else {
                const float4* wp4 = (const float4*)((w == 1 ? svx : svy) + lc * 32);
                #pragma unroll
                for (int j = 0; j < 8; j++) {
                    float4 v = pp4[j], u = wp4[j];
                    acc = fmaf(v.x, u.x, acc); acc = fmaf(v.y, u.y, acc);
                    acc = fmaf(v.z, u.z, acc); acc = fmaf(v.w, u.w, acc);
                }
            }
            sG[it * 4 + lc][ch] = acc;
        }
    }
    __syncthreads();

    if (tid < NCHF) {
        float coef = c_CM[tid / 3];
        float excl = 0.0f;
        #pragma unroll
        for (int c = 0; c < NCH2; c++) {
            float v = sG[c][tid];
            sG[c][tid] = excl * coef;
            excl += v;
        }
    }
    __syncthreads();

    const int b = bh >> 7, h = bh & 127;
    for (int it = 0; it < 8; it++) {
        int t = it * 128 + tid;
        float2 q = g_q[base + t];

        const float4* kp = &skv[(it * 4 + warp) << 5];
        float num0 = 0.f, num1 = 0.f, den = 0.f;

        int n = lane + 1, n4 = n & ~3;
        int s = 0;
        for (; s < n4; s += 4) {
            #pragma unroll
            for (int j = 0; j < 4; j++) {
                float4 kv = kp[s + j];
                float p = ex2f(fmaf(q.x, kv.x, q.y * kv.y));
                num0 = fmaf(p, kv.z, num0);
                num1 = fmaf(p, kv.w, num1);
                den += p;
            }
        }
        for (; s < n; s++) {
            float4 kv = kp[s];
            float p = ex2f(fmaf(q.x, kv.x, q.y * kv.y));
            num0 = fmaf(p, kv.z, num0);
            num1 = fmaf(p, kv.w, num1);
            den += p;
        }

        const float* S = sG[it * 4 + warp];
        float ca = q.x * 0.69314718f, sa = q.y * 0.69314718f;
        den  += S[0];
        num0 += S[1];
        num1 += S[2];
        float c2a = ca + ca;
        float cp = 1.f, sp = 0.f, cc = ca, cs = sa;
        #pragma unroll
        for (int m = 1; m <= 8; m++) {
            int b3 = 3 * (2 * m - 1);
            den  = fmaf(cc, S[b3 + 0], den);
            num0 = fmaf(cc, S[b3 + 1], num0);
            num1 = fmaf(cc, S[b3 + 2], num1);
            den  = fmaf(cs, S[b3 + 3], den);
            num0 = fmaf(cs, S[b3 + 4], num0);
            num1 = fmaf(cs, S[b3 + 5], num1);
            float cn = fmaf(c2a, cc, -cp);
            float sn = fmaf(c2a, cs, -sp);
            cp = cc; sp = cs; cc = cn; cs = sn;
        }

        float inv = 1.0f / den;
        float o0 = num0 * inv, o1 = num1 * inv;
        __nv_bfloat162 h2 = __floats2bfloat162_rn(o0, o1);
        __nv_bfloat162 l2 = __floats2bfloat162_rn(o0 - __bfloat162float(h2.x),
                                                  o1 - __bfloat162float(h2.y));
        size_t yo = ((size_t)(b * TT + t) * CC + 2 * h) >> 1;
        g_yh[yo] = h2;
        g_yl[yo] = l2;
    }
}

// ---------------------------------------------------------------------------
extern "C" void kernel_launch(void* const* d_in, const int* in_sizes, int n_in,
                              void* d_out, int out_size)
{
    const float* x      = (const float*)d_in[0];   // (2,1024,256)
    const float* w_qkv  = (const float*)d_in[1];   // (768,256)
    const float* w_proj = (const float*)d_in[2];   // (256,256)
    const float* qn_w   = (const float*)d_in[3];   // (2,)
    const float* kn_w   = (const float*)d_in[4];   // (2,)
    float* out = (float*)d_out;                    // (2,1024,256)

    __nv_bfloat162 *xh, *xl, *wh, *wl, *ph, *pl;
    cudaGetSymbolAddress((void**)&xh, g_xh); cudaGetSymbolAddress((void**)&xl, g_xl);
    cudaGetSymbolAddress((void**)&wh, g_wh); cudaGetSymbolAddress((void**)&wl, g_wl);
    cudaGetSymbolAddress((void**)&ph, g_ph); cudaGetSymbolAddress((void**)&pl, g_pl);

    cudaFuncSetAttribute(qkv_mma,  cudaFuncAttributeMaxDynamicSharedMemorySize, SM_DYN);
    cudaFuncSetAttribute(proj_mma, cudaFuncAttributeMaxDynamicSharedMemorySize, SM_DYN);

    // pre-split fp32 -> bf16 hi/lo
    convert_split<<<(BB*TT*CC/2)/256, 256>>>(x, xh, xl, BB*TT*CC/2);
    convert_split<<<(3*CC*CC/2)/256, 256>>>(w_qkv, wh, wl, 3*CC*CC/2);
    convert_split<<<(CC*CC/2)/256, 256>>>(w_proj, ph, pl, CC*CC/2);

    // qkv = x @ w_qkv^T with fused rmsnorm/split epilogue -> g_q/g_kx/...
    qkv_mma<<<dim3(12, 32), 256, SM_DYN>>>(qn_w, kn_w);
    // fused Fourier attention -> g_yh/g_yl (bf16 hi/lo)
    fourier_attn<<<NBH, 128>>>();
    // out = y @ w_proj^T
    proj_mma<<<dim3(4, 32), 256, SM_DYN>>>(out);
}

// round 17
// speedup vs baseline: 3.9090x; 1.2369x over previous
#include <cuda_runtime.h>
#include <cuda_bf16.h>
#include <cstdint>
#include <cstddef>

// Problem constants: B=2, T=1024, C=256, head_dim=2, H=128
#define BB 2
#define TT 1024
#define CC 256
#define HH 128
#define NBH (BB*HH)      // 256
#define NCH2 32          // 32-chunks for intra-exact attention
#define NFF 17           // Fourier features: 1, {cos,sin}(m*beta) m=1..8
#define NCHF (NFF*3)     // 51 channels

// Scratch (no allocations allowed -> __device__ globals)
__device__ float2 g_q  [NBH * TT];
__device__ float  g_kx [NBH * TT];
__device__ float  g_ky [NBH * TT];
__device__ float  g_vx [NBH * TT];
__device__ float  g_vy [NBH * TT];
// bf16 hi/lo pre-split operands
__device__ __nv_bfloat162 g_xh[BB*TT*CC/2],  g_xl[BB*TT*CC/2];    // x
__device__ __nv_bfloat162 g_wh[3*CC*CC/2],   g_wl[3*CC*CC/2];     // w_qkv
__device__ __nv_bfloat162 g_ph[CC*CC/2],     g_pl[CC*CC/2];       // w_proj
__device__ __nv_bfloat162 g_yh[BB*TT*CC/2],  g_yl[BB*TT*CC/2];    // attn out

// Fourier coefficients: C0=I0(sqrt2), Cm=2*Im(sqrt2)
__constant__ float c_CM[NFF] = {
    1.56608293f,
    1.79848892f, 1.79848892f,
    0.58871897f, 0.58871897f,
    0.13333993f, 0.13333993f,
    0.02300557f, 0.02300557f,
    3.2007638e-3f, 3.2007638e-3f,
    3.7280500e-4f, 3.7280500e-4f,
    3.7328000e-5f, 3.7328000e-5f,
    3.2767400e-6f, 3.2767400e-6f
};

__device__ __forceinline__ float ex2f(float x) {
    float r; asm("ex2.approx.f32 %0, %1;" : "=f"(r) : "f"(x)); return r;
}
__device__ __forceinline__ uint32_t smem_u32(const void* p) {
    uint32_t a;
    asm("{ .reg .u64 t; cvta.to.shared.u64 t, %1; cvt.u32.u64 %0, t; }"
        : "=r"(a) : "l"(p));
    return a;
}

// Portable Ampere-style bf16 MMA (valid PTX for plain sm_103 target)
#define MMA16816(c, a, b) \
    asm volatile("mma.sync.aligned.m16n8k16.row.col.f32.bf16.bf16.f32 " \
        "{%0,%1,%2,%3}, {%4,%5,%6,%7}, {%8,%9}, {%0,%1,%2,%3};" \
        : "+f"((c)[0]), "+f"((c)[1]), "+f"((c)[2]), "+f"((c)[3]) \
        : "r"((a)[0]), "r"((a)[1]), "r"((a)[2]), "r"((a)[3]), \
          "r"((b)[0]), "r"((b)[1]))

// cp.async (portable sm_80+)
#define CP_ASYNC16(dst, src) \
    asm volatile("cp.async.ca.shared.global [%0], [%1], 16;" \
                 :: "r"(dst), "l"(src) : "memory")
#define CP_COMMIT() asm volatile("cp.async.commit_group;" ::: "memory")
#define CP_WAIT0()  asm volatile("cp.async.wait_group 0;" ::: "memory")
#define CP_WAIT1()  asm volatile("cp.async.wait_group 1;" ::: "memory")
#define CP_WAIT2()  asm volatile("cp.async.wait_group 2;" ::: "memory")

// Shared tile geometry: bf16 [rows][64] with XOR swizzle on bits 4-6.
__device__ __forceinline__ int swzb(int row, int colbyte) {
    return row * 128 + (colbyte ^ ((row & 7) << 4));
}

// Per-stage smem layout (32KB/stage, 3 stages = 96KB dynamic)
#define ST_AH 0
#define ST_AL 8192
#define ST_BH 16384
#define ST_BL 24576
#define ST_SIZE 32768
#define SM_DYN (3*ST_SIZE)

// ---------------------------------------------------------------------------
// Fused fp32 -> bf16 hi/lo split for x, w_qkv, w_proj (one launch).
// float2 tasks: x 262144 | w_qkv 98304 | w_proj 32768  (total 393216)
// ---------------------------------------------------------------------------
__global__ void __launch_bounds__(256) convert_all(const float* __restrict__ x,
                                                   const float* __restrict__ wq,
                                                   const float* __restrict__ wp)
{
    int i = blockIdx.x * blockDim.x + threadIdx.x;
    const float* src;
    __nv_bfloat162 *hi, *lo;
    int off;
    if (i < 262144)      { src = x;  hi = g_xh; lo = g_xl; off = i; }
    else if (i < 360448) { src = wq; hi = g_wh; lo = g_wl; off = i - 262144; }
    else                 { src = wp; hi = g_ph; lo = g_pl; off = i - 360448; }
    float2 v = ((const float2*)src)[off];
    __nv_bfloat162 h = __floats2bfloat162_rn(v.x, v.y);
    float hx = __bfloat162float(h.x), hy = __bfloat162float(h.y);
    __nv_bfloat162 l = __floats2bfloat162_rn(v.x - hx, v.y - hy);
    hi[off] = h;
    lo[off] = l;
}

// ---------------------------------------------------------------------------
// Issue cp.async loads for one 64-wide K chunk (A: 64 rows, B: 64 rows).
// ---------------------------------------------------------------------------
__device__ __forceinline__ void issue_chunk(uint32_t smb, int st,
                                            const __nv_bfloat16* __restrict__ Ah,
                                            const __nv_bfloat16* __restrict__ Al,
                                            const __nv_bfloat16* __restrict__ Bh,
                                            const __nv_bfloat16* __restrict__ Bl,
                                            int m0, int n0, int k0, int tid)
{
    const uint32_t sb = smb + st * ST_SIZE;
    #pragma unroll
    for (int it = 0; it < 8; it++) {
        int p = it * 256 + tid;
        const __nv_bfloat16* src;
        uint32_t dst;
        if (p < 1024) {                  // A: 64 rows x 16 segs (8 hi, 8 lo)
            int row = p >> 4, u = p & 15, seg = u & 7;
            src = ((u < 8) ? Ah : Al) + (size_t)(m0 + row) * 256 + k0 + seg * 8;
            dst = sb + ((u < 8) ? ST_AH : ST_AL) + swzb(row, seg * 16);
        } else {                         // B: 64 rows x 16 segs
            int q = p - 1024;
            int row = q >> 4, u = q & 15, seg = u & 7;
            src = ((u < 8) ? Bh : Bl) + (size_t)(n0 + row) * 256 + k0 + seg * 8;
            dst = sb + ((u < 8) ? ST_BH : ST_BL) + swzb(row, seg * 16);
        }
        CP_ASYNC16(dst, src);
    }
    CP_COMMIT();
}

// ---------------------------------------------------------------------------
// Compute one K chunk from smem stage st. 64x64 CTA tile, warps 2(m) x 4(n).
// ---------------------------------------------------------------------------
__device__ __forceinline__ void compute_chunk(const unsigned char* sm, int st,
                                              int wm, int wn, int g, int tg,
                                              float acc[2][2][4])
{
    const unsigned char* s = sm + st * ST_SIZE;
    #pragma unroll
    for (int ks = 0; ks < 4; ks++) {
        const int cb = ks * 32 + tg * 4;
        uint32_t ah[2][4], al[2][4], bh[2][2], bl[2][2];
        #pragma unroll
        for (int i = 0; i < 2; i++) {
            int r = wm * 32 + i * 16 + g;
            int o00 = swzb(r, cb), o10 = swzb(r + 8, cb);
            int o01 = swzb(r, cb + 16), o11 = swzb(r + 8, cb + 16);
            ah[i][0] = *(const uint32_t*)(s + ST_AH + o00);
            ah[i][1] = *(const uint32_t*)(s + ST_AH + o10);
            ah[i][2] = *(const uint32_t*)(s + ST_AH + o01);
            ah[i][3] = *(const uint32_t*)(s + ST_AH + o11);
            al[i][0] = *(const uint32_t*)(s + ST_AL + o00);
            al[i][1] = *(const uint32_t*)(s + ST_AL + o10);
            al[i][2] = *(const uint32_t*)(s + ST_AL + o01);
            al[i][3] = *(const uint32_t*)(s + ST_AL + o11);
        }
        #pragma unroll
        for (int j = 0; j < 2; j++) {
            int rn = wn * 16 + j * 8 + g;
            int o0 = swzb(rn, cb), o1 = swzb(rn, cb + 16);
            bh[j][0] = *(const uint32_t*)(s + ST_BH + o0);
            bh[j][1] = *(const uint32_t*)(s + ST_BH + o1);
            bl[j][0] = *(const uint32_t*)(s + ST_BL + o0);
            bl[j][1] = *(const uint32_t*)(s + ST_BL + o1);
        }
        #pragma unroll
        for (int i = 0; i < 2; i++)
            #pragma unroll
            for (int j = 0; j < 2; j++) {
                MMA16816(acc[i][j], ah[i], bh[j]);
                MMA16816(acc[i][j], ah[i], bl[j]);
                MMA16816(acc[i][j], al[i], bh[j]);
            }
    }
}

// Triple-buffered mainloop over K=256 in 4 chunks of 64.
__device__ __forceinline__ void mma_nt_pipe(unsigned char* sm,
                                            const __nv_bfloat16* Ah, const __nv_bfloat16* Al,
                                            const __nv_bfloat16* Bh, const __nv_bfloat16* Bl,
                                            int m0, int n0,
                                            int wm, int wn, int g, int tg,
                                            float acc[2][2][4])
{
    const int tid = threadIdx.x;
    const uint32_t smb = smem_u32(sm);

    issue_chunk(smb, 0, Ah, Al, Bh, Bl, m0, n0, 0,   tid);
    issue_chunk(smb, 1, Ah, Al, Bh, Bl, m0, n0, 64,  tid);
    issue_chunk(smb, 2, Ah, Al, Bh, Bl, m0, n0, 128, tid);
    #pragma unroll
    for (int ci = 0; ci < 4; ci++) {
        if (ci <= 1) CP_WAIT2();
        else if (ci == 2) CP_WAIT1();
        else CP_WAIT0();
        __syncthreads();
        compute_chunk(sm, ci % 3, wm, wn, g, tg, acc);
        if (ci == 0) {
            __syncthreads();       // all warps done reading stage 0
            issue_chunk(smb, 0, Ah, Al, Bh, Bl, m0, n0, 192, tid);
        }
    }
}

// ---------------------------------------------------------------------------
// qkv GEMM + fused RMSNorm/split epilogue. grid (12, 32), 256 threads.
// ---------------------------------------------------------------------------
__global__ void __launch_bounds__(256) qkv_mma(const float* __restrict__ qn_w,
                                               const float* __restrict__ kn_w)
{
    extern __shared__ __align__(16) unsigned char sm[];
    const int m0 = blockIdx.y * 64, n0 = blockIdx.x * 64;
    const int tid = threadIdx.x;
    const int wid = tid >> 5, lane = tid & 31;
    const int wm = wid & 1, wn = wid >> 1;
    const int g = lane >> 2, tg = lane & 3;
    float acc[2][2][4] = {};

    mma_nt_pipe(sm, (const __nv_bfloat16*)g_xh, (const __nv_bfloat16*)g_xl,
                    (const __nv_bfloat16*)g_wh, (const __nv_bfloat16*)g_wl,
                m0, n0, wm, wn, g, tg, acc);

    const int third = blockIdx.x >> 2;                 // 0=q, 1=k, 2=v
    const int hb = (blockIdx.x & 3) * 32 + wn * 8 + tg;

    if (third == 0) {
        const float L2 = 1.02013946f;                  // log2(e)/sqrt(2)
        const float w0 = qn_w[0] * L2, w1 = qn_w[1] * L2;
        #pragma unroll
        for (int i = 0; i < 2; i++)
            #pragma unroll
            for (int j = 0; j < 2; j++) {
                int h = hb + j * 4;
                #pragma unroll
                for (int hf = 0; hf < 2; hf++) {
                    int m = m0 + wm * 32 + i * 16 + g + hf * 8;
                    float qx = acc[i][j][2 * hf], qy = acc[i][j][2 * hf + 1];
                    float r = rsqrtf(0.5f * (qx * qx + qy * qy) + 1e-6f);
                    g_q[((size_t)((m >> 10) * HH + h)) * TT + (m & 1023)] =
                        make_float2(qx * r * w0, qy * r * w1);
                }
            }
    } else if (third == 1) {
        const float w0 = kn_w[0], w1 = kn_w[1];
        #pragma unroll
        for (int i = 0; i < 2; i++)
            #pragma unroll
            for (int j = 0; j < 2; j++) {
                int h = hb + j * 4;
                #pragma unroll
                for (int hf = 0; hf < 2; hf++) {
                    int m = m0 + wm * 32 + i * 16 + g + hf * 8;
                    float kx = acc[i][j][2 * hf], ky = acc[i][j][2 * hf + 1];
                    float r = rsqrtf(0.5f * (kx * kx + ky * ky) + 1e-6f);
                    size_t o = ((size_t)((m >> 10) * HH + h)) * TT + (m & 1023);
                    g_kx[o] = kx * r * w0;
                    g_ky[o] = ky * r * w1;
                }
            }
    } else {
        #pragma unroll
        for (int i = 0; i < 2; i++)
            #pragma unroll
            for (int j = 0; j < 2; j++) {
                int h = hb + j * 4;
                #pragma unroll
                for (int hf = 0; hf < 2; hf++) {
                    int m = m0 + wm * 32 + i * 16 + g + hf * 8;
                    size_t o = ((size_t)((m >> 10) * HH + h)) * TT + (m & 1023);
                    g_vx[o] = acc[i][j][2 * hf];
                    g_vy[o] = acc[i][j][2 * hf + 1];
                }
            }
    }
}

// ---------------------------------------------------------------------------
// proj GEMM. grid (4, 32), 256 threads.
// ---------------------------------------------------------------------------
__global__ void __launch_bounds__(256) proj_mma(float* __restrict__ out)
{
    extern __shared__ __align__(16) unsigned char sm[];
    const int m0 = blockIdx.y * 64, n0 = blockIdx.x * 64;
    const int tid = threadIdx.x;
    const int wid = tid >> 5, lane = tid & 31;
    const int wm = wid & 1, wn = wid >> 1;
    const int g = lane >> 2, tg = lane & 3;
    float acc[2][2][4] = {};

    mma_nt_pipe(sm, (const __nv_bfloat16*)g_yh, (const __nv_bfloat16*)g_yl,
                    (const __nv_bfloat16*)g_ph, (const __nv_bfloat16*)g_pl,
                m0, n0, wm, wn, g, tg, acc);

    #pragma unroll
    for (int i = 0; i < 2; i++)
        #pragma unroll
        for (int j = 0; j < 2; j++) {
            int n = n0 + wn * 16 + j * 8 + 2 * tg;
            #pragma unroll
            for (int hf = 0; hf < 2; hf++) {
                int m = m0 + wm * 32 + i * 16 + g + hf * 8;
                *(float2*)(out + (size_t)m * CC + n) =
                    make_float2(acc[i][j][2 * hf], acc[i][j][2 * hf + 1]);
            }
        }
}

// ---------------------------------------------------------------------------
// Fused Fourier attention, 256 threads/block, one block per (b,h).
// Phase 1: 4 x 256-position tiles -> 51-channel sums per 32-chunk.
// Phase 2: exclusive chunk scan (Bessel coeffs folded).
// Phase 3: per query: exact ex2 over own 32-chunk (warp=chunk) + Fourier dot.
// ---------------------------------------------------------------------------
__global__ void __launch_bounds__(256) fourier_attn()
{
    __shared__ __align__(16) float  sPsi[NFF][264];   // feature x 256 positions
    __shared__ __align__(16) float  svx[256], svy[256];
    __shared__ float  sG[NCH2][NCHF];
    __shared__ __align__(16) float4 skv[TT];
    const int bh = blockIdx.x, tid = threadIdx.x;
    const int warp = tid >> 5, lane = tid & 31;
    const size_t base = (size_t)bh * TT;

    // ---- Phase 1 ----
    for (int it = 0; it < 4; it++) {
        int s = it * 256 + tid;
        float kx = g_kx[base + s], ky = g_ky[base + s];
        float vx = g_vx[base + s], vy = g_vy[base + s];
        __syncthreads();                    // previous iteration's readers done
        skv[s] = make_float4(kx, ky, vx, vy);
        svx[tid] = vx; svy[tid] = vy;
        // k on radius-sqrt2 circle: cos(beta)=kx/sqrt2, sin(beta)=ky/sqrt2
        float cb = kx * 0.70710678f, sb = ky * 0.70710678f;
        float c2b = cb + cb;
        sPsi[0][tid] = 1.0f;
        sPsi[1][tid] = cb;
        sPsi[2][tid] = sb;
        float cp = 1.0f, sp = 0.0f, cc = cb, cs = sb;
        #pragma unroll
        for (int m = 2; m <= 8; m++) {      // Chebyshev recurrence
            float cn = fmaf(c2b, cc, -cp);
            float sn = fmaf(c2b, cs, -sp);
            sPsi[2 * m - 1][tid] = cn;
            sPsi[2 * m][tid]     = sn;
            cp = cc; sp = cs; cc = cn; cs = sn;
        }
        __syncthreads();
        // 8 chunks x 51 channels = 408 reduction tasks over 256 threads
        for (int task = tid; task < 8 * NCHF; task += 256) {
            int lc = task / NCHF;
            int ch = task - lc * NCHF;
            int f  = ch / 3, w = ch - 3 * f;
            const float4* pp4 = (const float4*)&sPsi[f][lc * 32];
            float acc = 0.0f;
            if (w == 0) {
                #pragma unroll
                for (int j = 0; j < 8; j++) {
                    float4 v = pp4[j];
                    acc += (v.x + v.y) + (v.z + v.w);
                }
            } else {
                const float4* wp4 = (const float4*)((w == 1 ? svx : svy) + lc * 32);
                #pragma unroll
                for (int j = 0; j < 8; j++) {
                    float4 v = pp4[j], u = wp4[j];
                    acc = fmaf(v.x, u.x, acc); acc = fmaf(v.y, u.y, acc);
                    acc = fmaf(v.z, u.z, acc); acc = fmaf(v.w, u.w, acc);
                }
            }
            sG[it * 8 + lc][ch] = acc;
        }
    }
    __syncthreads();

    // ---- Phase 2: exclusive scan over chunks, fold Bessel coefficient ----
    if (tid < NCHF) {
        float coef = c_CM[tid / 3];
        float excl = 0.0f;
        #pragma unroll
        for (int c = 0; c < NCH2; c++) {
            float v = sG[c][tid];
            sG[c][tid] = excl * coef;
            excl += v;
        }
    }
    __syncthreads();

    // ---- Phase 3 ----
    const int b = bh >> 7, h = bh & 127;
    for (int it = 0; it < 4; it++) {
        int t = it * 256 + tid;
        float2 q = g_q[base + t];

        const float4* kp = &skv[(it * 8 + warp) << 5];
        float num0 = 0.f, num1 = 0.f, den = 0.f;

        // exact intra-chunk (q pre-scaled by log2e/sqrt2 -> bare ex2)
        int n = lane + 1, n4 = n & ~3;
        int s = 0;
        for (; s < n4; s += 4) {
            #pragma unroll
            for (int j = 0; j < 4; j++) {
                float4 kv = kp[s + j];
                float p = ex2f(fmaf(q.x, kv.x, q.y * kv.y));
                num0 = fmaf(p, kv.z, num0);
                num1 = fmaf(p, kv.w, num1);
                den += p;
            }
        }
        for (; s < n; s++) {
            float4 kv = kp[s];
            float p = ex2f(fmaf(q.x, kv.x, q.y * kv.y));
            num0 = fmaf(p, kv.z, num0);
            num1 = fmaf(p, kv.w, num1);
            den += p;
        }

        // inter-chunk Fourier dot
        const float* S = sG[it * 8 + warp];
        float ca = q.x * 0.69314718f, sa = q.y * 0.69314718f;
        den  += S[0];
        num0 += S[1];
        num1 += S[2];
        float c2a = ca + ca;
        float cp = 1.f, sp = 0.f, cc = ca, cs = sa;
        #pragma unroll
        for (int m = 1; m <= 8; m++) {
            int b3 = 3 * (2 * m - 1);
            den  = fmaf(cc, S[b3 + 0], den);
            num0 = fmaf(cc, S[b3 + 1], num0);
            num1 = fmaf(cc, S[b3 + 2], num1);
            den  = fmaf(cs, S[b3 + 3], den);
            num0 = fmaf(cs, S[b3 + 4], num0);
            num1 = fmaf(cs, S[b3 + 5], num1);
            float cn = fmaf(c2a, cc, -cp);
            float sn = fmaf(c2a, cs, -sp);
            cp = cc; sp = cs; cc = cn; cs = sn;
        }

        float inv = 1.0f / den;
        float o0 = num0 * inv, o1 = num1 * inv;
        // write bf16 hi/lo split directly (proj GEMM operand)
        __nv_bfloat162 h2 = __floats2bfloat162_rn(o0, o1);
        __nv_bfloat162 l2 = __floats2bfloat162_rn(o0 - __bfloat162float(h2.x),
                                                  o1 - __bfloat162float(h2.y));
        size_t yo = ((size_t)(b * TT + t) * CC + 2 * h) >> 1;
        g_yh[yo] = h2;
        g_yl[yo] = l2;
    }
}

// ---------------------------------------------------------------------------
extern "C" void kernel_launch(void* const* d_in, const int* in_sizes, int n_in,
                              void* d_out, int out_size)
{
    const float* x      = (const float*)d_in[0];   // (2,1024,256)
    const float* w_qkv  = (const float*)d_in[1];   // (768,256)
    const float* w_proj = (const float*)d_in[2];   // (256,256)
    const float* qn_w   = (const float*)d_in[3];   // (2,)
    const float* kn_w   = (const float*)d_in[4];   // (2,)
    float* out = (float*)d_out;                    // (2,1024,256)

    cudaFuncSetAttribute(qkv_mma,  cudaFuncAttributeMaxDynamicSharedMemorySize, SM_DYN);
    cudaFuncSetAttribute(proj_mma, cudaFuncAttributeMaxDynamicSharedMemorySize, SM_DYN);

    // pre-split fp32 -> bf16 hi/lo (single fused launch)
    convert_all<<<1536, 256>>>(x, w_qkv, w_proj);

    // qkv = x @ w_qkv^T with fused rmsnorm/split epilogue -> g_q/g_kx/...
    qkv_mma<<<dim3(12, 32), 256, SM_DYN>>>(qn_w, kn_w);
    // fused Fourier attention -> g_yh/g_yl (bf16 hi/lo)
    fourier_attn<<<NBH, 256>>>();
    // out = y @ w_proj^T
    proj_mma<<<dim3(4, 32), 256, SM_DYN>>>(out);
}